// round 9
// baseline (speedup 1.0000x reference)
#include <cuda_runtime.h>
#include <cuda_bf16.h>
#include <math.h>
#include <stdint.h>

// Problem constants
#define BB 4
#define SS 4096
#define DD 128
#define HH 8
#define KK 128
#define MM 256

#define BS   (BB*SS)        // 16384
#define BSH  (BB*SS*HH)     // 131072
#define HK   (HH*KK)        // 1024
#define HM   (HH*MM)        // 2048

typedef __nv_bfloat16 bf16;

// -------- scratch (static device globals) --------
__device__ float g_Xn  [BS*DD];
__device__ float g_part[2097152];              // kv split-K partials
__device__ float g_ks  [BB*HH*MM];
__device__ float g_dn  [BSH];
__device__ float g_ao  [BS*DD];
__device__ float g_tB  [BS*DD];

// bf16 hi/lo pairs (hi at [0], lo at [1])
__device__ bf16 b_Q   [2][BS*DD];
__device__ bf16 b_Xn  [2][BS*DD];
__device__ bf16 b_WqT [2][HK*DD];
__device__ bf16 b_WkT [2][HK*DD];
__device__ bf16 b_WvT [2][HK*DD];
__device__ bf16 b_WoT [2][DD*HK];
__device__ bf16 b_proj[2][MM*KK];
__device__ bf16 b_fw0T[2][DD*DD];
__device__ bf16 b_fw1T[2][DD*DD];
__device__ bf16 b_q   [2][BS*HK];
__device__ bf16 b_k   [2][BS*HK];
__device__ bf16 b_qp  [2][(size_t)BSH*MM];     // [b,s,h,m]
__device__ bf16 b_kpT [2][(size_t)BSH*MM];     // [b,h,m,s]
__device__ bf16 b_vT  [2][BS*HK];              // [b,h,k,s]
__device__ bf16 b_kvT [2][BB*HH*KK*MM];        // [b,h,k,m]
__device__ bf16 b_attn[2][(size_t)BS*HK];      // [b,s,h,k]
__device__ bf16 b_tA  [2][BS*DD];

// ================= asm helpers =================
__device__ __forceinline__ uint32_t smem_u32(const void* p) {
    uint32_t a;
    asm("{ .reg .u64 t; cvta.to.shared.u64 t, %1; cvt.u32.u64 %0, t; }" : "=r"(a) : "l"(p));
    return a;
}
#define CP_ASYNC16(dst, src) asm volatile("cp.async.cg.shared.global [%0], [%1], 16;" :: "r"(dst), "l"(__cvta_generic_to_global(src)))
#define CP_COMMIT()          asm volatile("cp.async.commit_group;")
#define CP_WAIT(n)           asm volatile("cp.async.wait_group %0;" :: "n"(n))

__device__ __forceinline__ void ldsm4(uint32_t* r, uint32_t a) {
    asm volatile("ldmatrix.sync.aligned.m8n8.x4.shared.b16 {%0,%1,%2,%3}, [%4];"
        : "=r"(r[0]), "=r"(r[1]), "=r"(r[2]), "=r"(r[3]) : "r"(a));
}
__device__ __forceinline__ void mma_bf16(float* d, const uint32_t* a, const uint32_t* b) {
    asm volatile("mma.sync.aligned.m16n8k16.row.col.f32.bf16.bf16.f32 "
        "{%0,%1,%2,%3}, {%4,%5,%6,%7}, {%8,%9}, {%0,%1,%2,%3};"
        : "+f"(d[0]), "+f"(d[1]), "+f"(d[2]), "+f"(d[3])
        : "r"(a[0]), "r"(a[1]), "r"(a[2]), "r"(a[3]), "r"(b[0]), "r"(b[1]));
}
__device__ __forceinline__ void split_bf16(float v, bf16& h, bf16& l) {
    h = __float2bfloat16(v);
    l = __float2bfloat16(v - __bfloat162float(h));
}

// ---------------- tile loader: bf16 global -> SW128 SMEM ----------------
// Tile [128 rows, 64 c] bf16, 128B/row, swizzled. 256 threads; 16B cp.async.
__device__ __forceinline__ void load_tile(uint32_t sU,
    const bf16* __restrict__ G, int ld, int base0, int k0, int tid)
{
    #pragma unroll
    for (int i = 0; i < 4; i++) {
        int idx = tid + i*256;                  // 1024 chunks of 16B
        int r = idx >> 3, c16 = idx & 7;
        const bf16* src = G + (size_t)(base0 + r)*ld + k0 + c16*8;
        int off = r*128 + c16*16;
        int sw = off ^ ((off >> 3) & 0x70);
        CP_ASYNC16(sU + sw, src);
    }
}

// fragment load for one k16 step (ks): A = 8 ldsm4 (hi+lo), B = 4 ldsm4
__device__ __forceinline__ void load_frags(int ks,
    uint32_t aH, uint32_t aL, uint32_t bH, uint32_t bL,
    int rA, int cA, int rB, int cB,
    uint32_t afh[4][4], uint32_t afl[4][4], uint32_t bfh[4][2], uint32_t bfl[4][2])
{
    #pragma unroll
    for (int mi = 0; mi < 4; mi++) {
        int row = rA + mi*16;
        int sw = row*128 + (((ks*2 + cA) ^ (row & 7)) * 16);
        ldsm4(afh[mi], aH + sw);
        ldsm4(afl[mi], aL + sw);
    }
    #pragma unroll
    for (int nj = 0; nj < 2; nj++) {
        int row = rB + nj*16;
        int sw = row*128 + (((ks*2 + cB) ^ (row & 7)) * 16);
        ldsm4(&bfh[nj*2][0], bH + sw);
        ldsm4(&bfl[nj*2][0], bL + sw);
    }
}

// ================= bf16-split warp-MMA GEMM, 3-stage cp.async, 256 threads =================
// 128x128 CTA tile, K-tiles of 64, 8 warps 2(m)x4(n), warp tile 64m x 32n.
// Register fragment double-buffering across k16 steps.
// 3-term split: AhiBhi + AhiBlo + AloBhi, fp32 accum.
// EPI 0: (acc + bias[col]) * alpha
// EPI 1: elu(acc + bias[col])
// EPI 2: (elu(acc)+1) * alpha                      (qp)
// EPI 3: acc (split-K partial)
// EPI 4: acc * dn[(b*S+row)*8+h]                   (attn)
// EPI 5: (elu(acc)+1) * alpha * maskf[b*S+col]     (kpT; token = column)
// EPI 6: acc + bias[h*128+row]                     (vT; row bias)
template<int EPI, int NSPLIT, bool OUTB>
__global__ void __launch_bounds__(256) tgemm(
    const bf16* __restrict__ Ah, const bf16* __restrict__ Al,
    const bf16* __restrict__ Bh, const bf16* __restrict__ Bl,
    float* __restrict__ C, bf16* __restrict__ Ch, bf16* __restrict__ Cl,
    const float* __restrict__ bias, const int* __restrict__ mask,
    const float* __restrict__ dn, float alpha,
    int Kd, int lda, int ldb, int ldc,
    long long sAb, long long sAh2, long long sBb, long long sBh2,
    long long sCb, long long sCh2, long long sCs)
{
    extern __shared__ char dyn[];
    const int ASZ = 128*128;          // 16KB per half tile
    const int BUFSZ = 4*ASZ;          // Ahi, Alo, Bhi, Blo = 64KB

    uint32_t dynU = smem_u32(dyn);
    uint32_t smU = (dynU + 1023u) & ~1023u;

    int tid = threadIdx.x;
    int lane = tid & 31, wid = tid >> 5;
    int wm = (wid & 1) * 64, wn = (wid >> 1) * 32;

    int z = blockIdx.z;
    int split = z % NSPLIT, bh = z / NSPLIT;
    int b = bh >> 3, h = bh & 7;
    Ah += (long long)b*sAb + (long long)h*sAh2;
    Al += (long long)b*sAb + (long long)h*sAh2;
    Bh += (long long)b*sBb + (long long)h*sBh2;
    Bl += (long long)b*sBb + (long long)h*sBh2;
    long long coff = (long long)b*sCb + (long long)h*sCh2 + (long long)split*sCs;
    if (OUTB) { Ch += coff; Cl += coff; } else { C += coff; }
    int kchunk = Kd / NSPLIT;
    int kbeg = split * kchunk;
    int nk = kchunk / 64;
    int m0 = blockIdx.y * 128, n0 = blockIdx.x * 128;

    float acc[4][4][4] = {};

    auto copy_stage = [&](int st, int k0) {
        uint32_t dU = smU + st*BUFSZ;
        load_tile(dU,         Ah, lda, m0, k0, tid);
        load_tile(dU + ASZ,   Al, lda, m0, k0, tid);
        load_tile(dU + 2*ASZ, Bh, ldb, n0, k0, tid);
        load_tile(dU + 3*ASZ, Bl, ldb, n0, k0, tid);
    };

    copy_stage(0, kbeg);            CP_COMMIT();
    copy_stage(1, kbeg + 64);       CP_COMMIT();

    // ldsm addressing
    int rA = wm + (lane & 15);
    int cA = lane >> 4;
    int rB = wn + (lane & 7) + ((lane >> 4) & 1) * 8;
    int cB = (lane >> 3) & 1;

    uint32_t afh[2][4][4], afl[2][4][4], bfh[2][4][2], bfl[2][4][2];

    for (int it = 0; it < nk; it++) {
        if (it < nk - 1) { CP_WAIT(1); } else { CP_WAIT(0); }
        __syncthreads();
        if (it + 2 < nk) {
            copy_stage((it + 2) % 3, kbeg + (it+2)*64);
            CP_COMMIT();
        }
        uint32_t aH = smU + (it % 3)*BUFSZ;
        uint32_t aL = aH + ASZ;
        uint32_t bH = aH + 2*ASZ;
        uint32_t bL = aH + 3*ASZ;

        load_frags(0, aH, aL, bH, bL, rA, cA, rB, cB,
                   afh[0], afl[0], bfh[0], bfl[0]);
        #pragma unroll
        for (int ks = 0; ks < 4; ks++) {
            int cur = ks & 1;
            if (ks < 3)
                load_frags(ks + 1, aH, aL, bH, bL, rA, cA, rB, cB,
                           afh[cur ^ 1], afl[cur ^ 1], bfh[cur ^ 1], bfl[cur ^ 1]);
            #pragma unroll
            for (int mi = 0; mi < 4; mi++)
                #pragma unroll
                for (int ni = 0; ni < 4; ni++) {
                    mma_bf16(acc[mi][ni], afh[cur][mi], bfh[cur][ni]);
                    mma_bf16(acc[mi][ni], afh[cur][mi], bfl[cur][ni]);
                    mma_bf16(acc[mi][ni], afl[cur][mi], bfh[cur][ni]);
                }
        }
        __syncthreads();
    }

    // ---------------- epilogue ----------------
    #pragma unroll
    for (int mi = 0; mi < 4; mi++) {
        int r0 = m0 + wm + mi*16 + (lane >> 2);
        int r1 = r0 + 8;
        float f0 = 1.0f, f1 = 1.0f;               // row factors
        if (EPI == 4) {
            f0 = dn[((size_t)(b*SS + r0))*8 + h];
            f1 = dn[((size_t)(b*SS + r1))*8 + h];
        } else if (EPI == 6) {
            f0 = bias[(h << 7) + r0];
            f1 = bias[(h << 7) + r1];
        }
        #pragma unroll
        for (int ni = 0; ni < 4; ni++) {
            int c0 = n0 + wn + ni*8 + (lane & 3)*2;
            float d0 = acc[mi][ni][0], d1 = acc[mi][ni][1];
            float d2 = acc[mi][ni][2], d3 = acc[mi][ni][3];
            if (EPI == 0) {
                float b0 = bias ? bias[c0] : 0.0f, b1 = bias ? bias[c0+1] : 0.0f;
                d0 = (d0 + b0)*alpha; d1 = (d1 + b1)*alpha;
                d2 = (d2 + b0)*alpha; d3 = (d3 + b1)*alpha;
            } else if (EPI == 1) {
                float b0 = bias[c0], b1 = bias[c0+1];
                d0 += b0; d1 += b1; d2 += b0; d3 += b1;
                d0 = d0 > 0.0f ? d0 : expm1f(d0);
                d1 = d1 > 0.0f ? d1 : expm1f(d1);
                d2 = d2 > 0.0f ? d2 : expm1f(d2);
                d3 = d3 > 0.0f ? d3 : expm1f(d3);
            } else if (EPI == 2) {
                d0 = (d0 > 0.0f ? d0 + 1.0f : expf(d0)) * alpha;
                d1 = (d1 > 0.0f ? d1 + 1.0f : expf(d1)) * alpha;
                d2 = (d2 > 0.0f ? d2 + 1.0f : expf(d2)) * alpha;
                d3 = (d3 > 0.0f ? d3 + 1.0f : expf(d3)) * alpha;
            } else if (EPI == 4) {
                d0 *= f0; d1 *= f0; d2 *= f1; d3 *= f1;
            } else if (EPI == 5) {
                float m0f = (float)mask[b*SS + c0];
                float m1f = (float)mask[b*SS + c0 + 1];
                d0 = (d0 > 0.0f ? d0 + 1.0f : expf(d0)) * alpha * m0f;
                d1 = (d1 > 0.0f ? d1 + 1.0f : expf(d1)) * alpha * m1f;
                d2 = (d2 > 0.0f ? d2 + 1.0f : expf(d2)) * alpha * m0f;
                d3 = (d3 > 0.0f ? d3 + 1.0f : expf(d3)) * alpha * m1f;
            } else if (EPI == 6) {
                d0 += f0; d1 += f0; d2 += f1; d3 += f1;
            }
            if (OUTB) {
                bf16 h0, l0, h1, l1, h2, l2, h3, l3;
                split_bf16(d0, h0, l0); split_bf16(d1, h1, l1);
                split_bf16(d2, h2, l2); split_bf16(d3, h3, l3);
                *reinterpret_cast<__nv_bfloat162*>(Ch + (size_t)r0*ldc + c0) = __nv_bfloat162(h0, h1);
                *reinterpret_cast<__nv_bfloat162*>(Cl + (size_t)r0*ldc + c0) = __nv_bfloat162(l0, l1);
                *reinterpret_cast<__nv_bfloat162*>(Ch + (size_t)r1*ldc + c0) = __nv_bfloat162(h2, h3);
                *reinterpret_cast<__nv_bfloat162*>(Cl + (size_t)r1*ldc + c0) = __nv_bfloat162(l2, l3);
            } else {
                *reinterpret_cast<float2*>(C + (size_t)r0*ldc + c0) = make_float2(d0, d1);
                *reinterpret_cast<float2*>(C + (size_t)r1*ldc + c0) = make_float2(d2, d3);
            }
        }
    }
}

// ---------------- converts ----------------
__global__ void conv_kernel(const float* __restrict__ src, bf16* __restrict__ hi,
                            bf16* __restrict__ lo, int n)
{
    int i = blockIdx.x*256 + threadIdx.x;
    if (i < n) { bf16 h, l; split_bf16(src[i], h, l); hi[i] = h; lo[i] = l; }
}
// transpose-convert three same-shape matrices in one launch (blockIdx.y selects)
__global__ void convT3_kernel(const float* __restrict__ s0, const float* __restrict__ s1,
                              const float* __restrict__ s2,
                              bf16* __restrict__ h0, bf16* __restrict__ l0,
                              bf16* __restrict__ h1, bf16* __restrict__ l1,
                              bf16* __restrict__ h2, bf16* __restrict__ l2,
                              int R, int C)
{
    const float* src = blockIdx.y == 0 ? s0 : (blockIdx.y == 1 ? s1 : s2);
    bf16* hi = blockIdx.y == 0 ? h0 : (blockIdx.y == 1 ? h1 : h2);
    bf16* lo = blockIdx.y == 0 ? l0 : (blockIdx.y == 1 ? l1 : l2);
    if (src == nullptr) return;
    int i = blockIdx.x*256 + threadIdx.x;
    if (i < R*C) {
        int r = i / C, c = i % C;
        bf16 h, l; split_bf16(src[i], h, l);
        hi[(size_t)c*R + r] = h; lo[(size_t)c*R + r] = l;
    }
}
__global__ void convT_kernel(const float* __restrict__ src, bf16* __restrict__ hi,
                             bf16* __restrict__ lo, int R, int C)
{
    int i = blockIdx.x*256 + threadIdx.x;
    if (i < R*C) {
        int r = i / C, c = i % C;
        bf16 h, l; split_bf16(src[i], h, l);
        hi[(size_t)c*R + r] = h; lo[(size_t)c*R + r] = l;
    }
}

// ---------------- LayerNorm helpers ----------------
__device__ __forceinline__ float block_ln(float x, int t, float* smv, float eps,
                                          const float* g, const float* b2)
{
    float s = x;
    #pragma unroll
    for (int o = 16; o; o >>= 1) s += __shfl_down_sync(0xffffffffu, s, o);
    if ((t & 31) == 0) smv[t >> 5] = s;
    __syncthreads();
    float mu = (smv[0] + smv[1] + smv[2] + smv[3]) * (1.0f/128.0f);
    float d = x - mu;
    float s2 = d * d;
    __syncthreads();
    #pragma unroll
    for (int o = 16; o; o >>= 1) s2 += __shfl_down_sync(0xffffffffu, s2, o);
    if ((t & 31) == 0) smv[t >> 5] = s2;
    __syncthreads();
    float var = (smv[0] + smv[1] + smv[2] + smv[3]) * (1.0f/128.0f);
    __syncthreads();
    return d * rsqrtf(var + eps) * g[t] + b2[t];
}

__global__ void ln_kernel(const float* __restrict__ in1,
                          const float* __restrict__ gamma, const float* __restrict__ beta,
                          float* __restrict__ outf, bf16* __restrict__ outh, bf16* __restrict__ outl)
{
    int row = blockIdx.x;
    int t = threadIdx.x;
    __shared__ float smv[4];
    float x = in1[(size_t)row*DD + t];
    float y = block_ln(x, t, smv, 1e-3f, gamma, beta);
    size_t idx = (size_t)row*DD + t;
    if (outf) outf[idx] = y;
    if (outh) { bf16 h, l; split_bf16(y, h, l); outh[idx] = h; outl[idx] = l; }
}

// fused: y1 = LN(Xn + ao*mask; g2) ; y2 = LN(y1; g0) -> bf16 hi/lo only
__global__ void ln_double_kernel(const float* __restrict__ Xn, const float* __restrict__ ao,
                                 const int* __restrict__ mask,
                                 const float* __restrict__ g2, const float* __restrict__ b2,
                                 const float* __restrict__ g0, const float* __restrict__ b0,
                                 bf16* __restrict__ outh, bf16* __restrict__ outl)
{
    int row = blockIdx.x;
    int t = threadIdx.x;
    __shared__ float smv[4];
    float mf = (float)mask[row];
    float x = Xn[(size_t)row*DD + t] + ao[(size_t)row*DD + t] * mf;
    float y1 = block_ln(x, t, smv, 1e-3f, g2, b2);
    float y2 = block_ln(y1, t, smv, 1e-3f, g0, b0);
    size_t idx = (size_t)row*DD + t;
    bf16 h, l; split_bf16(y2, h, l);
    outh[idx] = h; outl[idx] = l;
}

// ---------------- kv reduce + transpose: part[bh][8][m256][k128] -> kvT[bh][k][m] ----------------
__global__ void reduce_kvT_kernel(const float* __restrict__ part,
                                  bf16* __restrict__ hi, bf16* __restrict__ lo)
{
    int bh = blockIdx.x;
    int tm = (blockIdx.y >> 1) * 64;
    int tk = (blockIdx.y & 1) * 64;
    __shared__ float t[64][65];
    const float* p = part + (size_t)bh*8*32768;
    int tid = threadIdx.x;
    #pragma unroll
    for (int i = 0; i < 16; i++) {
        int idx = tid + i*256;
        int r = idx >> 6, c = idx & 63;
        float s = 0.0f;
        #pragma unroll
        for (int sp = 0; sp < 8; sp++) s += p[sp*32768 + (tm+r)*128 + tk+c];
        t[c][r] = s;
    }
    __syncthreads();
    bf16* H = hi + (size_t)bh*KK*MM;
    bf16* L = lo + (size_t)bh*KK*MM;
    #pragma unroll
    for (int i = 0; i < 16; i++) {
        int idx = tid + i*256;
        int kk2 = idx >> 6, mm2 = idx & 63;
        float s = t[kk2][mm2];
        bf16 h, l; split_bf16(s, h, l);
        H[(size_t)(tk+kk2)*MM + tm+mm2] = h;
        L[(size_t)(tk+kk2)*MM + tm+mm2] = l;
    }
}

// ---------------- ksum from kpT ----------------
__global__ void ksum_kernel(const bf16* __restrict__ kph, const bf16* __restrict__ kpl,
                            float* __restrict__ ks)
{
    int bh = blockIdx.x;
    int wid = threadIdx.x >> 5, lane = threadIdx.x & 31;
    int m = blockIdx.y * 8 + wid;
    const bf16* H = kph + ((size_t)bh*MM + m)*SS;
    const bf16* L = kpl + ((size_t)bh*MM + m)*SS;
    float s = 0.0f;
    for (int i = lane; i < SS; i += 32)
        s += __bfloat162float(H[i]) + __bfloat162float(L[i]);
    #pragma unroll
    for (int o = 16; o; o >>= 1) s += __shfl_down_sync(0xffffffffu, s, o);
    if (lane == 0) ks[bh*MM + m] = s;
}

// ---------------- denom ----------------
__global__ void denom_kernel(const bf16* __restrict__ qph, const bf16* __restrict__ qpl,
                             const float* __restrict__ ksum, float* __restrict__ denom)
{
    int warp = threadIdx.x >> 5, lane = threadIdx.x & 31;
    int r = blockIdx.x * 8 + warp;
    size_t qb = (size_t)r * MM;
    int b = r / (SS * HH);
    int h = r & 7;
    const float* ks = ksum + (b*HH + h) * MM;
    float s = 0.0f;
    for (int i = lane; i < MM; i += 32) {
        float qv = __bfloat162float(qph[qb + i]) + __bfloat162float(qpl[qb + i]);
        s += qv * ks[i];
    }
    #pragma unroll
    for (int o = 16; o; o >>= 1) s += __shfl_down_sync(0xffffffffu, s, o);
    if (lane == 0) denom[r] = 1.0f / (s + 1e-6f);
}

// ---------------- host-side launch ----------------
template<typename T>
static T* sym_addr(const void* sym)
{
    void* p = nullptr;
    cudaGetSymbolAddress(&p, sym);
    return (T*)p;
}

#define SMEM_REQ (3*4*128*128 + 1024)   // 197632

extern "C" void kernel_launch(void* const* d_in, const int* in_sizes, int n_in,
                              void* d_out, int out_size)
{
    (void)in_sizes; (void)n_in; (void)out_size;
    const float* Q      = (const float*)d_in[0];
    const float* X      = (const float*)d_in[1];
    const int*   mask   = (const int*)  d_in[2];
    const float* Wq     = (const float*)d_in[3];
    const float* bq     = (const float*)d_in[4];
    const float* Wk     = (const float*)d_in[5];
    const float* bk     = (const float*)d_in[6];
    const float* Wv     = (const float*)d_in[7];
    const float* bv     = (const float*)d_in[8];
    const float* Wo     = (const float*)d_in[9];
    const float* bo     = (const float*)d_in[10];
    const float* proj   = (const float*)d_in[11];
    const float* ln1_g  = (const float*)d_in[12];
    const float* ln1_b  = (const float*)d_in[13];
    const float* ln2_g  = (const float*)d_in[14];
    const float* ln2_b  = (const float*)d_in[15];
    const float* fln0_g = (const float*)d_in[16];
    const float* fln0_b = (const float*)d_in[17];
    const float* f_w0   = (const float*)d_in[18];
    const float* f_b0   = (const float*)d_in[19];
    const float* fln1_g = (const float*)d_in[20];
    const float* fln1_b = (const float*)d_in[21];
    const float* f_w1   = (const float*)d_in[22];
    const float* f_b1   = (const float*)d_in[23];
    float* out = (float*)d_out;

    float* Xn   = sym_addr<float>(g_Xn);
    float* part = sym_addr<float>(g_part);
    float* ks   = sym_addr<float>(g_ks);
    float* dn   = sym_addr<float>(g_dn);
    float* ao   = sym_addr<float>(g_ao);
    float* tB   = sym_addr<float>(g_tB);

    bf16* bQ    = sym_addr<bf16>(b_Q);      bf16* bQl    = bQ    + (size_t)BS*DD;
    bf16* bXn   = sym_addr<bf16>(b_Xn);     bf16* bXnl   = bXn   + (size_t)BS*DD;
    bf16* bWqT  = sym_addr<bf16>(b_WqT);    bf16* bWqTl  = bWqT  + (size_t)HK*DD;
    bf16* bWkT  = sym_addr<bf16>(b_WkT);    bf16* bWkTl  = bWkT  + (size_t)HK*DD;
    bf16* bWvT  = sym_addr<bf16>(b_WvT);    bf16* bWvTl  = bWvT  + (size_t)HK*DD;
    bf16* bWoT  = sym_addr<bf16>(b_WoT);    bf16* bWoTl  = bWoT  + (size_t)DD*HK;
    bf16* bproj = sym_addr<bf16>(b_proj);   bf16* bprojl = bproj + (size_t)MM*KK;
    bf16* bfw0T = sym_addr<bf16>(b_fw0T);   bf16* bfw0Tl = bfw0T + (size_t)DD*DD;
    bf16* bfw1T = sym_addr<bf16>(b_fw1T);   bf16* bfw1Tl = bfw1T + (size_t)DD*DD;
    bf16* bq_h  = sym_addr<bf16>(b_q);      bf16* bq_l   = bq_h  + (size_t)BS*HK;
    bf16* bk_h  = sym_addr<bf16>(b_k);      bf16* bk_l   = bk_h  + (size_t)BS*HK;
    bf16* bqp_h = sym_addr<bf16>(b_qp);     bf16* bqp_l  = bqp_h + (size_t)BSH*MM;
    bf16* bkpT_h= sym_addr<bf16>(b_kpT);    bf16* bkpT_l = bkpT_h+ (size_t)BSH*MM;
    bf16* bvT_h = sym_addr<bf16>(b_vT);     bf16* bvT_l  = bvT_h + (size_t)BS*HK;
    bf16* bkvT_h= sym_addr<bf16>(b_kvT);    bf16* bkvT_l = bkvT_h+ (size_t)BB*HH*KK*MM;
    bf16* bat_h = sym_addr<bf16>(b_attn);   bf16* bat_l  = bat_h + (size_t)BS*HK;
    bf16* btA_h = sym_addr<bf16>(b_tA);     bf16* btA_l  = btA_h + (size_t)BS*DD;

    const float scale_q    = 0.08838834764831845f;  // 1/sqrt(128)
    const float inv_sqrt_m = 0.0625f;               // 1/sqrt(256)

    cudaFuncSetAttribute(tgemm<0,1,true >, cudaFuncAttributeMaxDynamicSharedMemorySize, SMEM_REQ);
    cudaFuncSetAttribute(tgemm<2,1,true >, cudaFuncAttributeMaxDynamicSharedMemorySize, SMEM_REQ);
    cudaFuncSetAttribute(tgemm<5,1,true >, cudaFuncAttributeMaxDynamicSharedMemorySize, SMEM_REQ);
    cudaFuncSetAttribute(tgemm<6,1,true >, cudaFuncAttributeMaxDynamicSharedMemorySize, SMEM_REQ);
    cudaFuncSetAttribute(tgemm<3,8,false>, cudaFuncAttributeMaxDynamicSharedMemorySize, SMEM_REQ);
    cudaFuncSetAttribute(tgemm<4,1,true >, cudaFuncAttributeMaxDynamicSharedMemorySize, SMEM_REQ);
    cudaFuncSetAttribute(tgemm<0,1,false>, cudaFuncAttributeMaxDynamicSharedMemorySize, SMEM_REQ);
    cudaFuncSetAttribute(tgemm<1,1,false>, cudaFuncAttributeMaxDynamicSharedMemorySize, SMEM_REQ);

    // 0. converts (merged: QKV weights in one launch, FFN weights in one)
    conv_kernel<<<(BS*DD + 255)/256, 256>>>(Q, bQ, bQl, BS*DD);
    conv_kernel<<<(MM*KK + 255)/256, 256>>>(proj, bproj, bprojl, MM*KK);
    convT3_kernel<<<dim3((DD*HK + 255)/256, 3), 256>>>(
        Wq, Wk, Wv, bWqT, bWqTl, bWkT, bWkTl, bWvT, bWvTl, DD, HK);
    convT_kernel<<<(HK*DD + 255)/256, 256>>>(Wo, bWoT, bWoTl, HK, DD);
    convT3_kernel<<<dim3((DD*DD + 255)/256, 3), 256>>>(
        f_w0, f_w1, nullptr, bfw0T, bfw0Tl, bfw1T, bfw1Tl, nullptr, nullptr, DD, DD);

    // 1. Xn = LN(X; ln1)
    ln_kernel<<<BS, 128>>>(X, ln1_g, ln1_b, Xn, bXn, bXnl);

    // 2-3. q, k projections -> bf16 hi/lo [BS, HK]
    tgemm<0,1,true><<<dim3(HK/128, BS/128, 1), 256, SMEM_REQ>>>(
        bQ, bQl, bWqT, bWqTl, nullptr, bq_h, bq_l, bq, nullptr, nullptr, scale_q,
        DD, DD, DD, HK, 0,0,0,0, 0,0,0);
    tgemm<0,1,true><<<dim3(HK/128, BS/128, 1), 256, SMEM_REQ>>>(
        bXn, bXnl, bWkT, bWkTl, nullptr, bk_h, bk_l, bk, nullptr, nullptr, 1.0f,
        DD, DD, DD, HK, 0,0,0,0, 0,0,0);

    // 4. vT[b,h,k,s] = Wv^T(h) @ Xn^T(b) + bv[h,k]
    tgemm<6,1,true><<<dim3(SS/128, 1, 32), 256, SMEM_REQ>>>(
        bWvT, bWvTl, bXn, bXnl, nullptr, bvT_h, bvT_l, bv, nullptr, nullptr, 1.0f,
        DD, DD, DD, SS,
        0, (long long)KK*DD, (long long)SS*DD, 0,
        (long long)HH*KK*SS, (long long)KK*SS, 0);

    // 5. qp[b,s,h,m] = (elu(q @ proj^T)+1)/sqrt(M)
    tgemm<2,1,true><<<dim3(MM/128, BSH/128, 1), 256, SMEM_REQ>>>(
        bq_h, bq_l, bproj, bprojl, nullptr, bqp_h, bqp_l, nullptr, nullptr, nullptr, inv_sqrt_m,
        KK, KK, KK, MM, 0,0,0,0, 0,0,0);

    // 6. kpT[b,h,m,s] = (elu(proj @ k^T)+1)/sqrt(M) * mask[token=col]
    tgemm<5,1,true><<<dim3(SS/128, MM/128, 32), 256, SMEM_REQ>>>(
        bproj, bprojl, bk_h, bk_l, nullptr, bkpT_h, bkpT_l, nullptr, mask, nullptr, inv_sqrt_m,
        KK, KK, HK, SS,
        0, 0, (long long)SS*HK, KK,
        (long long)HH*MM*SS, (long long)MM*SS, 0);

    // 7. kv partials: A=kpT[m,s], B=vT[k,s], split-K=8 over s
    tgemm<3,8,false><<<dim3(1, MM/128, 32*8), 256, SMEM_REQ>>>(
        bkpT_h, bkpT_l, bvT_h, bvT_l, part, nullptr, nullptr, nullptr, nullptr, nullptr, 1.0f,
        SS, SS, SS, KK,
        (long long)HH*MM*SS, (long long)MM*SS, (long long)HH*KK*SS, (long long)KK*SS,
        2097152LL, 262144LL, 32768LL);
    reduce_kvT_kernel<<<dim3(32, 8), 256>>>(part, bkvT_h, bkvT_l);

    // 8. ksum from kpT
    ksum_kernel<<<dim3(32, 32), 256>>>(bkpT_h, bkpT_l, ks);

    // 9. denom
    denom_kernel<<<BSH/8, 256>>>(bqp_h, bqp_l, ks, dn);

    // 10. attn[b,s,h,k] = (qp @ kvT^T) * dn
    tgemm<4,1,true><<<dim3(1, SS/128, 32), 256, SMEM_REQ>>>(
        bqp_h, bqp_l, bkvT_h, bkvT_l, nullptr, bat_h, bat_l, nullptr, nullptr, dn, 1.0f,
        MM, HM, MM, HK,
        (long long)SS*HM, MM, (long long)HH*KK*MM, (long long)KK*MM,
        (long long)SS*HK, KK, 0);

    // 11. ao = attn @ WoT + bo
    tgemm<0,1,false><<<dim3(1, BS/128, 1), 256, SMEM_REQ>>>(
        bat_h, bat_l, bWoT, bWoTl, ao, nullptr, nullptr, bo, nullptr, nullptr, 1.0f,
        HK, HK, HK, DD, 0,0,0,0, 0,0,0);

    // 12+13. fused: out1 = LN(Xn+ao*mask; ln2); tA = LN(out1; fln0) -> bf16
    ln_double_kernel<<<BS, 128>>>(Xn, ao, mask, ln2_g, ln2_b, fln0_g, fln0_b, btA_h, btA_l);

    // 14-16. FFN
    tgemm<1,1,false><<<dim3(1, BS/128, 1), 256, SMEM_REQ>>>(
        btA_h, btA_l, bfw0T, bfw0Tl, tB, nullptr, nullptr, f_b0, nullptr, nullptr, 1.0f,
        DD, DD, DD, DD, 0,0,0,0, 0,0,0);
    ln_kernel<<<BS, 128>>>(tB, fln1_g, fln1_b, nullptr, btA_h, btA_l);
    tgemm<0,1,false><<<dim3(1, BS/128, 1), 256, SMEM_REQ>>>(
        btA_h, btA_l, bfw1T, bfw1Tl, out, nullptr, nullptr, f_b1, nullptr, nullptr, 1.0f,
        DD, DD, DD, DD, 0,0,0,0, 0,0,0);
}

// round 10
// speedup vs baseline: 1.0130x; 1.0130x over previous
#include <cuda_runtime.h>
#include <cuda_bf16.h>
#include <math.h>
#include <stdint.h>

// Problem constants
#define BB 4
#define SS 4096
#define DD 128
#define HH 8
#define KK 128
#define MM 256

#define BS   (BB*SS)        // 16384
#define BSH  (BB*SS*HH)     // 131072
#define HK   (HH*KK)        // 1024
#define HM   (HH*MM)        // 2048

typedef __nv_bfloat16 bf16;

// -------- scratch (static device globals) --------
__device__ float g_Xn  [BS*DD];
__device__ float g_part[2097152];              // kv split-K partials
__device__ float g_ks  [BB*HH*MM];
__device__ float g_ao  [BS*DD];
__device__ float g_tB  [BS*DD];

// bf16 hi/lo pairs (hi at [0], lo at [1])
__device__ bf16 b_Q   [2][BS*DD];
__device__ bf16 b_Xn  [2][BS*DD];
__device__ bf16 b_WqT [2][HK*DD];
__device__ bf16 b_WkT [2][HK*DD];
__device__ bf16 b_WvT [2][HK*DD];
__device__ bf16 b_WoT [2][DD*HK];
__device__ bf16 b_proj[2][MM*KK];
__device__ bf16 b_fw0T[2][DD*DD];
__device__ bf16 b_fw1T[2][DD*DD];
__device__ bf16 b_q   [2][BS*HK];
__device__ bf16 b_k   [2][BS*HK];
__device__ bf16 b_kpT [2][(size_t)BSH*MM];     // [b,h,m,s]
__device__ bf16 b_vT  [2][BS*HK];              // [b,h,k,s]
__device__ bf16 b_kvT [2][BB*HH*KK*MM];        // [b,h,k,m]
__device__ bf16 b_attn[2][(size_t)BS*HK];      // [b,s,h,k]
__device__ bf16 b_tA  [2][BS*DD];

// ================= asm helpers =================
__device__ __forceinline__ uint32_t smem_u32(const void* p) {
    uint32_t a;
    asm("{ .reg .u64 t; cvta.to.shared.u64 t, %1; cvt.u32.u64 %0, t; }" : "=r"(a) : "l"(p));
    return a;
}
#define CP_ASYNC16(dst, src) asm volatile("cp.async.cg.shared.global [%0], [%1], 16;" :: "r"(dst), "l"(__cvta_generic_to_global(src)))
#define CP_COMMIT()          asm volatile("cp.async.commit_group;")
#define CP_WAIT(n)           asm volatile("cp.async.wait_group %0;" :: "n"(n))

__device__ __forceinline__ void ldsm4(uint32_t* r, uint32_t a) {
    asm volatile("ldmatrix.sync.aligned.m8n8.x4.shared.b16 {%0,%1,%2,%3}, [%4];"
        : "=r"(r[0]), "=r"(r[1]), "=r"(r[2]), "=r"(r[3]) : "r"(a));
}
__device__ __forceinline__ void mma_bf16(float* d, const uint32_t* a, const uint32_t* b) {
    asm volatile("mma.sync.aligned.m16n8k16.row.col.f32.bf16.bf16.f32 "
        "{%0,%1,%2,%3}, {%4,%5,%6,%7}, {%8,%9}, {%0,%1,%2,%3};"
        : "+f"(d[0]), "+f"(d[1]), "+f"(d[2]), "+f"(d[3])
        : "r"(a[0]), "r"(a[1]), "r"(a[2]), "r"(a[3]), "r"(b[0]), "r"(b[1]));
}
__device__ __forceinline__ void split_bf16(float v, bf16& h, bf16& l) {
    h = __float2bfloat16(v);
    l = __float2bfloat16(v - __bfloat162float(h));
}

// ---------------- chunk-tile loader: [R rows x 64 c] bf16 -> swizzled smem ----------------
template<int R, int NTHR>
__device__ __forceinline__ void load_ct(uint32_t sU,
    const bf16* __restrict__ G, int ld, int base0, int k0, int tid)
{
    #pragma unroll
    for (int i = 0; i < (R*8)/NTHR; i++) {
        int idx = tid + i*NTHR;
        int r = idx >> 3, c16 = idx & 7;
        const bf16* src = G + (size_t)(base0 + r)*ld + k0 + c16*8;
        int off = r*128 + c16*16;
        int sw = off ^ ((off >> 3) & 0x70);
        CP_ASYNC16(sU + sw, src);
    }
}

// ================= bf16-split warp-MMA GEMM (R8 config: 512 thr, 3-stage) =================
// 128x128 CTA tile, K-tiles of 64, 16 warps 4(m)x4(n), warp tile 32m x 32n.
// EPI 0: (acc + bias[col]) * alpha
// EPI 1: elu(acc + bias[col])
// EPI 3: acc (split-K partial)
// EPI 5: (elu(acc)+1) * alpha * maskf[b*S+col]
// EPI 6: acc + bias[h*128+row]
template<int EPI, int NSPLIT, bool OUTB>
__global__ void __launch_bounds__(512) tgemm(
    const bf16* __restrict__ Ah, const bf16* __restrict__ Al,
    const bf16* __restrict__ Bh, const bf16* __restrict__ Bl,
    float* __restrict__ C, bf16* __restrict__ Ch, bf16* __restrict__ Cl,
    const float* __restrict__ bias, const int* __restrict__ mask,
    float alpha,
    int Kd, int lda, int ldb, int ldc,
    long long sAb, long long sAh2, long long sBb, long long sBh2,
    long long sCb, long long sCh2, long long sCs)
{
    extern __shared__ char dyn[];
    const int ASZ = 128*128;
    const int BUFSZ = 4*ASZ;

    uint32_t dynU = smem_u32(dyn);
    uint32_t smU = (dynU + 1023u) & ~1023u;

    int tid = threadIdx.x;
    int lane = tid & 31, wid = tid >> 5;
    int wm = (wid & 3) * 32, wn = (wid >> 2) * 32;

    int z = blockIdx.z;
    int split = z % NSPLIT, bh = z / NSPLIT;
    int b = bh >> 3, h = bh & 7;
    Ah += (long long)b*sAb + (long long)h*sAh2;
    Al += (long long)b*sAb + (long long)h*sAh2;
    Bh += (long long)b*sBb + (long long)h*sBh2;
    Bl += (long long)b*sBb + (long long)h*sBh2;
    long long coff = (long long)b*sCb + (long long)h*sCh2 + (long long)split*sCs;
    if (OUTB) { Ch += coff; Cl += coff; } else { C += coff; }
    int kchunk = Kd / NSPLIT;
    int kbeg = split * kchunk;
    int nk = kchunk / 64;
    int m0 = blockIdx.y * 128, n0 = blockIdx.x * 128;

    float acc[2][4][4] = {};

    auto copy_stage = [&](int st, int k0) {
        uint32_t dU = smU + st*BUFSZ;
        load_ct<128,512>(dU,         Ah, lda, m0, k0, tid);
        load_ct<128,512>(dU + ASZ,   Al, lda, m0, k0, tid);
        load_ct<128,512>(dU + 2*ASZ, Bh, ldb, n0, k0, tid);
        load_ct<128,512>(dU + 3*ASZ, Bl, ldb, n0, k0, tid);
    };

    copy_stage(0, kbeg);            CP_COMMIT();
    copy_stage(1, kbeg + 64);       CP_COMMIT();

    int rA = wm + (lane & 15);
    int cA = lane >> 4;
    int rB = wn + (lane & 7) + ((lane >> 4) & 1) * 8;
    int cB = (lane >> 3) & 1;

    for (int it = 0; it < nk; it++) {
        if (it < nk - 1) { CP_WAIT(1); } else { CP_WAIT(0); }
        __syncthreads();
        if (it + 2 < nk) {
            copy_stage((it + 2) % 3, kbeg + (it+2)*64);
            CP_COMMIT();
        }
        uint32_t aH = smU + (it % 3)*BUFSZ;
        uint32_t aL = aH + ASZ;
        uint32_t bH = aH + 2*ASZ;
        uint32_t bL = aH + 3*ASZ;
        #pragma unroll
        for (int ks = 0; ks < 4; ks++) {
            uint32_t afh[2][4], afl[2][4], bfh[4][2], bfl[4][2];
            #pragma unroll
            for (int mi = 0; mi < 2; mi++) {
                int row = rA + mi*16;
                int sw = row*128 + (((ks*2 + cA) ^ (row & 7)) * 16);
                ldsm4(afh[mi], aH + sw);
                ldsm4(afl[mi], aL + sw);
            }
            #pragma unroll
            for (int nj = 0; nj < 2; nj++) {
                int row = rB + nj*16;
                int sw = row*128 + (((ks*2 + cB) ^ (row & 7)) * 16);
                ldsm4(&bfh[nj*2][0], bH + sw);
                ldsm4(&bfl[nj*2][0], bL + sw);
            }
            #pragma unroll
            for (int mi = 0; mi < 2; mi++)
                #pragma unroll
                for (int ni = 0; ni < 4; ni++) {
                    mma_bf16(acc[mi][ni], afh[mi], bfh[ni]);
                    mma_bf16(acc[mi][ni], afh[mi], bfl[ni]);
                    mma_bf16(acc[mi][ni], afl[mi], bfh[ni]);
                }
        }
        __syncthreads();
    }

    // epilogue
    #pragma unroll
    for (int mi = 0; mi < 2; mi++) {
        int r0 = m0 + wm + mi*16 + (lane >> 2);
        int r1 = r0 + 8;
        float f0 = 1.0f, f1 = 1.0f;
        if (EPI == 6) {
            f0 = bias[(h << 7) + r0];
            f1 = bias[(h << 7) + r1];
        }
        #pragma unroll
        for (int ni = 0; ni < 4; ni++) {
            int c0 = n0 + wn + ni*8 + (lane & 3)*2;
            float d0 = acc[mi][ni][0], d1 = acc[mi][ni][1];
            float d2 = acc[mi][ni][2], d3 = acc[mi][ni][3];
            if (EPI == 0) {
                float b0 = bias ? bias[c0] : 0.0f, b1 = bias ? bias[c0+1] : 0.0f;
                d0 = (d0 + b0)*alpha; d1 = (d1 + b1)*alpha;
                d2 = (d2 + b0)*alpha; d3 = (d3 + b1)*alpha;
            } else if (EPI == 1) {
                float b0 = bias[c0], b1 = bias[c0+1];
                d0 += b0; d1 += b1; d2 += b0; d3 += b1;
                d0 = d0 > 0.0f ? d0 : expm1f(d0);
                d1 = d1 > 0.0f ? d1 : expm1f(d1);
                d2 = d2 > 0.0f ? d2 : expm1f(d2);
                d3 = d3 > 0.0f ? d3 : expm1f(d3);
            } else if (EPI == 5) {
                float m0f = (float)mask[b*SS + c0];
                float m1f = (float)mask[b*SS + c0 + 1];
                d0 = (d0 > 0.0f ? d0 + 1.0f : expf(d0)) * alpha * m0f;
                d1 = (d1 > 0.0f ? d1 + 1.0f : expf(d1)) * alpha * m1f;
                d2 = (d2 > 0.0f ? d2 + 1.0f : expf(d2)) * alpha * m0f;
                d3 = (d3 > 0.0f ? d3 + 1.0f : expf(d3)) * alpha * m1f;
            } else if (EPI == 6) {
                d0 += f0; d1 += f0; d2 += f1; d3 += f1;
            }
            if (OUTB) {
                bf16 h0, l0, h1, l1, h2, l2, h3, l3;
                split_bf16(d0, h0, l0); split_bf16(d1, h1, l1);
                split_bf16(d2, h2, l2); split_bf16(d3, h3, l3);
                *reinterpret_cast<__nv_bfloat162*>(Ch + (size_t)r0*ldc + c0) = __nv_bfloat162(h0, h1);
                *reinterpret_cast<__nv_bfloat162*>(Cl + (size_t)r0*ldc + c0) = __nv_bfloat162(l0, l1);
                *reinterpret_cast<__nv_bfloat162*>(Ch + (size_t)r1*ldc + c0) = __nv_bfloat162(h2, h3);
                *reinterpret_cast<__nv_bfloat162*>(Cl + (size_t)r1*ldc + c0) = __nv_bfloat162(l2, l3);
            } else {
                *reinterpret_cast<float2*>(C + (size_t)r0*ldc + c0) = make_float2(d0, d1);
                *reinterpret_cast<float2*>(C + (size_t)r1*ldc + c0) = make_float2(d2, d3);
            }
        }
    }
}

// ================= fused qp + denom + attn kernel (256 threads) =================
// Per (bh, s-tile of 64):
//  phase 1: qp[s64, m256] = (elu(q @ proj^T)+1)/sqrt(M) -> smem bf16 hi/lo (4 m-chunks)
//  denom:   dn[s] = 1/(qp[s,:]·ks + 1e-6)               -> smem
//  phase 2: attn[s64, k128] = (qp @ kvT^T) * dn         -> global bf16 hi/lo
// smem layout (bytes): QP_HI 0..32K, QP_LO 32K..64K, QT_HI 64K..80K, QT_LO 80K..96K,
//                      BBUF 96K + st*32K (hi 16K, lo 16K). total 160KB.
#define FA_QP_HI 0
#define FA_QP_LO 32768
#define FA_QT_HI 65536
#define FA_QT_LO 81920
#define FA_BBUF  98304
#define SMEM_FATTN (163840 + 1024)

__global__ void __launch_bounds__(256) fattn_kernel(
    const bf16* __restrict__ qh, const bf16* __restrict__ ql,
    const bf16* __restrict__ projh, const bf16* __restrict__ projl,
    const bf16* __restrict__ kvh, const bf16* __restrict__ kvl,
    const float* __restrict__ ksum,
    bf16* __restrict__ outh, bf16* __restrict__ outl)
{
    extern __shared__ char dyn[];
    __shared__ float dn_smem[64];
    uint32_t dynU = smem_u32(dyn);
    uint32_t smU = (dynU + 1023u) & ~1023u;

    int tid = threadIdx.x;
    int lane = tid & 31, wid = tid >> 5;
    int ws = wid & 1, wn = wid >> 1;          // 2(s) x 4(n) warps; warp tile 32 x 32

    int bh = blockIdx.z;
    int b = bh >> 3, h = bh & 7;
    int s0 = blockIdx.y * 64;

    const bf16* qhp = qh + ((size_t)(b*SS + s0))*HK + h*KK;   // [64 rows, ld HK]
    const bf16* qlp = ql + ((size_t)(b*SS + s0))*HK + h*KK;
    const bf16* kvhp = kvh + (size_t)bh*KK*MM;                // [128 rows, ld MM]
    const bf16* kvlp = kvl + (size_t)bh*KK*MM;
    const float* ksp = ksum + bh*MM;

    const float inv_sqrt_m = 0.0625f;

    // load q tile (64 rows x 128 k as 2 chunk-tiles, hi+lo)
    load_ct<64,256>(smU + FA_QT_HI,        qhp, HK, 0, 0,  tid);
    load_ct<64,256>(smU + FA_QT_HI + 8192, qhp, HK, 0, 64, tid);
    load_ct<64,256>(smU + FA_QT_LO,        qlp, HK, 0, 0,  tid);
    load_ct<64,256>(smU + FA_QT_LO + 8192, qlp, HK, 0, 64, tid);

    // B loader for iteration it: it<4 -> proj[mh*128 rows, kt*64]; it>=4 -> kvT chunk it-4
    auto loadB = [&](int it) {
        uint32_t dU = smU + FA_BBUF + (it & 1)*32768;
        if (it < 4) {
            int mh = it >> 1, kt = it & 1;
            load_ct<128,256>(dU,         projh, KK, mh*128, kt*64, tid);
            load_ct<128,256>(dU + 16384, projl, KK, mh*128, kt*64, tid);
        } else {
            int ch = it - 4;
            load_ct<128,256>(dU,         kvhp, MM, 0, ch*64, tid);
            load_ct<128,256>(dU + 16384, kvlp, MM, 0, ch*64, tid);
        }
    };

    loadB(0); CP_COMMIT();     // group 0: q tile + B0
    loadB(1); CP_COMMIT();     // group 1

    int rAl = ws*32 + (lane & 15);
    int cA  = lane >> 4;
    int rBl = wn*32 + (lane & 7) + ((lane >> 4) & 1) * 8;
    int cB  = (lane >> 3) & 1;

    float acc[2][4][4] = {};

    for (int it = 0; it < 8; it++) {
        if (it < 7) { CP_WAIT(1); } else { CP_WAIT(0); }
        __syncthreads();

        uint32_t aH, aL;
        if (it < 4) {
            int kt = it & 1;
            aH = smU + FA_QT_HI + kt*8192;
            aL = smU + FA_QT_LO + kt*8192;
        } else {
            int ch = it - 4;
            aH = smU + FA_QP_HI + ch*8192;
            aL = smU + FA_QP_LO + ch*8192;
        }
        uint32_t bH = smU + FA_BBUF + (it & 1)*32768;
        uint32_t bL = bH + 16384;

        #pragma unroll
        for (int ks = 0; ks < 4; ks++) {
            uint32_t afh[2][4], afl[2][4], bfh[4][2], bfl[4][2];
            #pragma unroll
            for (int mi = 0; mi < 2; mi++) {
                int row = rAl + mi*16;
                int sw = row*128 + (((ks*2 + cA) ^ (row & 7)) * 16);
                ldsm4(afh[mi], aH + sw);
                ldsm4(afl[mi], aL + sw);
            }
            #pragma unroll
            for (int nj = 0; nj < 2; nj++) {
                int row = rBl + nj*16;
                int sw = row*128 + (((ks*2 + cB) ^ (row & 7)) * 16);
                ldsm4(&bfh[nj*2][0], bH + sw);
                ldsm4(&bfl[nj*2][0], bL + sw);
            }
            #pragma unroll
            for (int mi = 0; mi < 2; mi++)
                #pragma unroll
                for (int ni = 0; ni < 4; ni++) {
                    mma_bf16(acc[mi][ni], afh[mi], bfh[ni]);
                    mma_bf16(acc[mi][ni], afh[mi], bfl[ni]);
                    mma_bf16(acc[mi][ni], afl[mi], bfh[ni]);
                }
        }

        // phase-1 epilogue after finishing both k-tiles of a half (it==1: mh0, it==3: mh1)
        if (it == 1 || it == 3) {
            int mh = it >> 1;
            #pragma unroll
            for (int mi = 0; mi < 2; mi++) {
                int r0 = ws*32 + mi*16 + (lane >> 2);
                int r1 = r0 + 8;
                #pragma unroll
                for (int ni = 0; ni < 4; ni++) {
                    int cl = wn*32 + ni*8 + (lane & 3)*2;
                    int mg = mh*128 + cl;
                    int chunk = mg >> 6, cin = mg & 63;
                    float d0 = acc[mi][ni][0], d1 = acc[mi][ni][1];
                    float d2 = acc[mi][ni][2], d3 = acc[mi][ni][3];
                    d0 = (d0 > 0.0f ? d0 + 1.0f : expf(d0)) * inv_sqrt_m;
                    d1 = (d1 > 0.0f ? d1 + 1.0f : expf(d1)) * inv_sqrt_m;
                    d2 = (d2 > 0.0f ? d2 + 1.0f : expf(d2)) * inv_sqrt_m;
                    d3 = (d3 > 0.0f ? d3 + 1.0f : expf(d3)) * inv_sqrt_m;
                    bf16 h0, l0, h1, l1, h2, l2, h3, l3;
                    split_bf16(d0, h0, l0); split_bf16(d1, h1, l1);
                    split_bf16(d2, h2, l2); split_bf16(d3, h3, l3);
                    int o0 = r0*128 + cin*2;  int sw0 = o0 ^ ((o0 >> 3) & 0x70);
                    int o1 = r1*128 + cin*2;  int sw1 = o1 ^ ((o1 >> 3) & 0x70);
                    *reinterpret_cast<__nv_bfloat162*>(dyn + (smU - dynU) + FA_QP_HI + chunk*8192 + sw0) = __nv_bfloat162(h0, h1);
                    *reinterpret_cast<__nv_bfloat162*>(dyn + (smU - dynU) + FA_QP_LO + chunk*8192 + sw0) = __nv_bfloat162(l0, l1);
                    *reinterpret_cast<__nv_bfloat162*>(dyn + (smU - dynU) + FA_QP_HI + chunk*8192 + sw1) = __nv_bfloat162(h2, h3);
                    *reinterpret_cast<__nv_bfloat162*>(dyn + (smU - dynU) + FA_QP_LO + chunk*8192 + sw1) = __nv_bfloat162(l2, l3);
                }
            }
            #pragma unroll
            for (int mi = 0; mi < 2; mi++)
                #pragma unroll
                for (int ni = 0; ni < 4; ni++)
                    #pragma unroll
                    for (int c = 0; c < 4; c++)
                        acc[mi][ni][c] = 0.0f;
        }

        __syncthreads();   // protects B-buffer reuse + QP visibility

        // denom after QP complete (it==3's sync just happened)
        if (it == 3) {
            int row = tid >> 2, part = tid & 3;
            char* base = dyn + (smU - dynU);
            float s = 0.0f;
            for (int j = 0; j < 64; j++) {
                int o = row*128 + j*2;
                int sw = o ^ ((o >> 3) & 0x70);
                float hv = __bfloat162float(*reinterpret_cast<bf16*>(base + FA_QP_HI + part*8192 + sw));
                float lv = __bfloat162float(*reinterpret_cast<bf16*>(base + FA_QP_LO + part*8192 + sw));
                s += (hv + lv) * ksp[part*64 + j];
            }
            s += __shfl_down_sync(0xffffffffu, s, 1);
            s += __shfl_down_sync(0xffffffffu, s, 2);
            if (part == 0) dn_smem[row] = 1.0f / (s + 1e-6f);
            __syncthreads();
        }

        if (it + 2 < 8) { loadB(it + 2); CP_COMMIT(); }
    }

    // phase-2 epilogue: attn out with dn
    #pragma unroll
    for (int mi = 0; mi < 2; mi++) {
        int r0 = ws*32 + mi*16 + (lane >> 2);
        int r1 = r0 + 8;
        float f0 = dn_smem[r0], f1 = dn_smem[r1];
        #pragma unroll
        for (int ni = 0; ni < 4; ni++) {
            int ck = wn*32 + ni*8 + (lane & 3)*2;
            float d0 = acc[mi][ni][0]*f0, d1 = acc[mi][ni][1]*f0;
            float d2 = acc[mi][ni][2]*f1, d3 = acc[mi][ni][3]*f1;
            bf16 h0, l0, h1, l1, h2, l2, h3, l3;
            split_bf16(d0, h0, l0); split_bf16(d1, h1, l1);
            split_bf16(d2, h2, l2); split_bf16(d3, h3, l3);
            size_t a0 = ((size_t)(b*SS + s0 + r0))*HK + h*KK + ck;
            size_t a1 = ((size_t)(b*SS + s0 + r1))*HK + h*KK + ck;
            *reinterpret_cast<__nv_bfloat162*>(outh + a0) = __nv_bfloat162(h0, h1);
            *reinterpret_cast<__nv_bfloat162*>(outl + a0) = __nv_bfloat162(l0, l1);
            *reinterpret_cast<__nv_bfloat162*>(outh + a1) = __nv_bfloat162(h2, h3);
            *reinterpret_cast<__nv_bfloat162*>(outl + a1) = __nv_bfloat162(l2, l3);
        }
    }
}

// ---------------- converts ----------------
__global__ void conv_kernel(const float* __restrict__ src, bf16* __restrict__ hi,
                            bf16* __restrict__ lo, int n)
{
    int i = blockIdx.x*256 + threadIdx.x;
    if (i < n) { bf16 h, l; split_bf16(src[i], h, l); hi[i] = h; lo[i] = l; }
}
__global__ void convT3_kernel(const float* __restrict__ s0, const float* __restrict__ s1,
                              const float* __restrict__ s2,
                              bf16* __restrict__ h0, bf16* __restrict__ l0,
                              bf16* __restrict__ h1, bf16* __restrict__ l1,
                              bf16* __restrict__ h2, bf16* __restrict__ l2,
                              int R, int C)
{
    const float* src = blockIdx.y == 0 ? s0 : (blockIdx.y == 1 ? s1 : s2);
    bf16* hi = blockIdx.y == 0 ? h0 : (blockIdx.y == 1 ? h1 : h2);
    bf16* lo = blockIdx.y == 0 ? l0 : (blockIdx.y == 1 ? l1 : l2);
    if (src == nullptr) return;
    int i = blockIdx.x*256 + threadIdx.x;
    if (i < R*C) {
        int r = i / C, c = i % C;
        bf16 h, l; split_bf16(src[i], h, l);
        hi[(size_t)c*R + r] = h; lo[(size_t)c*R + r] = l;
    }
}
__global__ void convT_kernel(const float* __restrict__ src, bf16* __restrict__ hi,
                             bf16* __restrict__ lo, int R, int C)
{
    int i = blockIdx.x*256 + threadIdx.x;
    if (i < R*C) {
        int r = i / C, c = i % C;
        bf16 h, l; split_bf16(src[i], h, l);
        hi[(size_t)c*R + r] = h; lo[(size_t)c*R + r] = l;
    }
}

// ---------------- LayerNorm ----------------
__device__ __forceinline__ float block_ln(float x, int t, float* smv, float eps,
                                          const float* g, const float* b2)
{
    float s = x;
    #pragma unroll
    for (int o = 16; o; o >>= 1) s += __shfl_down_sync(0xffffffffu, s, o);
    if ((t & 31) == 0) smv[t >> 5] = s;
    __syncthreads();
    float mu = (smv[0] + smv[1] + smv[2] + smv[3]) * (1.0f/128.0f);
    float d = x - mu;
    float s2 = d * d;
    __syncthreads();
    #pragma unroll
    for (int o = 16; o; o >>= 1) s2 += __shfl_down_sync(0xffffffffu, s2, o);
    if ((t & 31) == 0) smv[t >> 5] = s2;
    __syncthreads();
    float var = (smv[0] + smv[1] + smv[2] + smv[3]) * (1.0f/128.0f);
    __syncthreads();
    return d * rsqrtf(var + eps) * g[t] + b2[t];
}

__global__ void ln_kernel(const float* __restrict__ in1,
                          const float* __restrict__ gamma, const float* __restrict__ beta,
                          float* __restrict__ outf, bf16* __restrict__ outh, bf16* __restrict__ outl)
{
    int row = blockIdx.x;
    int t = threadIdx.x;
    __shared__ float smv[4];
    float x = in1[(size_t)row*DD + t];
    float y = block_ln(x, t, smv, 1e-3f, gamma, beta);
    size_t idx = (size_t)row*DD + t;
    if (outf) outf[idx] = y;
    if (outh) { bf16 h, l; split_bf16(y, h, l); outh[idx] = h; outl[idx] = l; }
}

__global__ void ln_double_kernel(const float* __restrict__ Xn, const float* __restrict__ ao,
                                 const int* __restrict__ mask,
                                 const float* __restrict__ g2, const float* __restrict__ b2,
                                 const float* __restrict__ g0, const float* __restrict__ b0,
                                 bf16* __restrict__ outh, bf16* __restrict__ outl)
{
    int row = blockIdx.x;
    int t = threadIdx.x;
    __shared__ float smv[4];
    float mf = (float)mask[row];
    float x = Xn[(size_t)row*DD + t] + ao[(size_t)row*DD + t] * mf;
    float y1 = block_ln(x, t, smv, 1e-3f, g2, b2);
    float y2 = block_ln(y1, t, smv, 1e-3f, g0, b0);
    size_t idx = (size_t)row*DD + t;
    bf16 h, l; split_bf16(y2, h, l);
    outh[idx] = h; outl[idx] = l;
}

// ---------------- kv reduce + transpose ----------------
__global__ void reduce_kvT_kernel(const float* __restrict__ part,
                                  bf16* __restrict__ hi, bf16* __restrict__ lo)
{
    int bh = blockIdx.x;
    int tm = (blockIdx.y >> 1) * 64;
    int tk = (blockIdx.y & 1) * 64;
    __shared__ float t[64][65];
    const float* p = part + (size_t)bh*8*32768;
    int tid = threadIdx.x;
    #pragma unroll
    for (int i = 0; i < 16; i++) {
        int idx = tid + i*256;
        int r = idx >> 6, c = idx & 63;
        float s = 0.0f;
        #pragma unroll
        for (int sp = 0; sp < 8; sp++) s += p[sp*32768 + (tm+r)*128 + tk+c];
        t[c][r] = s;
    }
    __syncthreads();
    bf16* H = hi + (size_t)bh*KK*MM;
    bf16* L = lo + (size_t)bh*KK*MM;
    #pragma unroll
    for (int i = 0; i < 16; i++) {
        int idx = tid + i*256;
        int kk2 = idx >> 6, mm2 = idx & 63;
        float s = t[kk2][mm2];
        bf16 h, l; split_bf16(s, h, l);
        H[(size_t)(tk+kk2)*MM + tm+mm2] = h;
        L[(size_t)(tk+kk2)*MM + tm+mm2] = l;
    }
}

// ---------------- ksum from kpT ----------------
__global__ void ksum_kernel(const bf16* __restrict__ kph, const bf16* __restrict__ kpl,
                            float* __restrict__ ks)
{
    int bh = blockIdx.x;
    int wid = threadIdx.x >> 5, lane = threadIdx.x & 31;
    int m = blockIdx.y * 8 + wid;
    const bf16* H = kph + ((size_t)bh*MM + m)*SS;
    const bf16* L = kpl + ((size_t)bh*MM + m)*SS;
    float s = 0.0f;
    for (int i = lane; i < SS; i += 32)
        s += __bfloat162float(H[i]) + __bfloat162float(L[i]);
    #pragma unroll
    for (int o = 16; o; o >>= 1) s += __shfl_down_sync(0xffffffffu, s, o);
    if (lane == 0) ks[bh*MM + m] = s;
}

// ---------------- host-side launch ----------------
template<typename T>
static T* sym_addr(const void* sym)
{
    void* p = nullptr;
    cudaGetSymbolAddress(&p, sym);
    return (T*)p;
}

#define SMEM_REQ (3*4*128*128 + 1024)   // 197632

extern "C" void kernel_launch(void* const* d_in, const int* in_sizes, int n_in,
                              void* d_out, int out_size)
{
    (void)in_sizes; (void)n_in; (void)out_size;
    const float* Q      = (const float*)d_in[0];
    const float* X      = (const float*)d_in[1];
    const int*   mask   = (const int*)  d_in[2];
    const float* Wq     = (const float*)d_in[3];
    const float* bq     = (const float*)d_in[4];
    const float* Wk     = (const float*)d_in[5];
    const float* bk     = (const float*)d_in[6];
    const float* Wv     = (const float*)d_in[7];
    const float* bv     = (const float*)d_in[8];
    const float* Wo     = (const float*)d_in[9];
    const float* bo     = (const float*)d_in[10];
    const float* proj   = (const float*)d_in[11];
    const float* ln1_g  = (const float*)d_in[12];
    const float* ln1_b  = (const float*)d_in[13];
    const float* ln2_g  = (const float*)d_in[14];
    const float* ln2_b  = (const float*)d_in[15];
    const float* fln0_g = (const float*)d_in[16];
    const float* fln0_b = (const float*)d_in[17];
    const float* f_w0   = (const float*)d_in[18];
    const float* f_b0   = (const float*)d_in[19];
    const float* fln1_g = (const float*)d_in[20];
    const float* fln1_b = (const float*)d_in[21];
    const float* f_w1   = (const float*)d_in[22];
    const float* f_b1   = (const float*)d_in[23];
    float* out = (float*)d_out;

    float* Xn   = sym_addr<float>(g_Xn);
    float* part = sym_addr<float>(g_part);
    float* ks   = sym_addr<float>(g_ks);
    float* ao   = sym_addr<float>(g_ao);
    float* tB   = sym_addr<float>(g_tB);

    bf16* bQ    = sym_addr<bf16>(b_Q);      bf16* bQl    = bQ    + (size_t)BS*DD;
    bf16* bXn   = sym_addr<bf16>(b_Xn);     bf16* bXnl   = bXn   + (size_t)BS*DD;
    bf16* bWqT  = sym_addr<bf16>(b_WqT);    bf16* bWqTl  = bWqT  + (size_t)HK*DD;
    bf16* bWkT  = sym_addr<bf16>(b_WkT);    bf16* bWkTl  = bWkT  + (size_t)HK*DD;
    bf16* bWvT  = sym_addr<bf16>(b_WvT);    bf16* bWvTl  = bWvT  + (size_t)HK*DD;
    bf16* bWoT  = sym_addr<bf16>(b_WoT);    bf16* bWoTl  = bWoT  + (size_t)DD*HK;
    bf16* bproj = sym_addr<bf16>(b_proj);   bf16* bprojl = bproj + (size_t)MM*KK;
    bf16* bfw0T = sym_addr<bf16>(b_fw0T);   bf16* bfw0Tl = bfw0T + (size_t)DD*DD;
    bf16* bfw1T = sym_addr<bf16>(b_fw1T);   bf16* bfw1Tl = bfw1T + (size_t)DD*DD;
    bf16* bq_h  = sym_addr<bf16>(b_q);      bf16* bq_l   = bq_h  + (size_t)BS*HK;
    bf16* bk_h  = sym_addr<bf16>(b_k);      bf16* bk_l   = bk_h  + (size_t)BS*HK;
    bf16* bkpT_h= sym_addr<bf16>(b_kpT);    bf16* bkpT_l = bkpT_h+ (size_t)BSH*MM;
    bf16* bvT_h = sym_addr<bf16>(b_vT);     bf16* bvT_l  = bvT_h + (size_t)BS*HK;
    bf16* bkvT_h= sym_addr<bf16>(b_kvT);    bf16* bkvT_l = bkvT_h+ (size_t)BB*HH*KK*MM;
    bf16* bat_h = sym_addr<bf16>(b_attn);   bf16* bat_l  = bat_h + (size_t)BS*HK;
    bf16* btA_h = sym_addr<bf16>(b_tA);     bf16* btA_l  = btA_h + (size_t)BS*DD;

    const float scale_q    = 0.08838834764831845f;  // 1/sqrt(128)
    const float inv_sqrt_m = 0.0625f;               // 1/sqrt(256)

    cudaFuncSetAttribute(tgemm<0,1,true >, cudaFuncAttributeMaxDynamicSharedMemorySize, SMEM_REQ);
    cudaFuncSetAttribute(tgemm<5,1,true >, cudaFuncAttributeMaxDynamicSharedMemorySize, SMEM_REQ);
    cudaFuncSetAttribute(tgemm<6,1,true >, cudaFuncAttributeMaxDynamicSharedMemorySize, SMEM_REQ);
    cudaFuncSetAttribute(tgemm<3,8,false>, cudaFuncAttributeMaxDynamicSharedMemorySize, SMEM_REQ);
    cudaFuncSetAttribute(tgemm<0,1,false>, cudaFuncAttributeMaxDynamicSharedMemorySize, SMEM_REQ);
    cudaFuncSetAttribute(tgemm<1,1,false>, cudaFuncAttributeMaxDynamicSharedMemorySize, SMEM_REQ);
    cudaFuncSetAttribute(fattn_kernel, cudaFuncAttributeMaxDynamicSharedMemorySize, SMEM_FATTN);

    // 0. converts
    conv_kernel<<<(BS*DD + 255)/256, 256>>>(Q, bQ, bQl, BS*DD);
    conv_kernel<<<(MM*KK + 255)/256, 256>>>(proj, bproj, bprojl, MM*KK);
    convT3_kernel<<<dim3((DD*HK + 255)/256, 3), 256>>>(
        Wq, Wk, Wv, bWqT, bWqTl, bWkT, bWkTl, bWvT, bWvTl, DD, HK);
    convT_kernel<<<(HK*DD + 255)/256, 256>>>(Wo, bWoT, bWoTl, HK, DD);
    convT3_kernel<<<dim3((DD*DD + 255)/256, 3), 256>>>(
        f_w0, f_w1, nullptr, bfw0T, bfw0Tl, bfw1T, bfw1Tl, nullptr, nullptr, DD, DD);

    // 1. Xn = LN(X; ln1)
    ln_kernel<<<BS, 128>>>(X, ln1_g, ln1_b, Xn, bXn, bXnl);

    // 2-3. q, k projections -> bf16 hi/lo [BS, HK]
    tgemm<0,1,true><<<dim3(HK/128, BS/128, 1), 512, SMEM_REQ>>>(
        bQ, bQl, bWqT, bWqTl, nullptr, bq_h, bq_l, bq, nullptr, scale_q,
        DD, DD, DD, HK, 0,0,0,0, 0,0,0);
    tgemm<0,1,true><<<dim3(HK/128, BS/128, 1), 512, SMEM_REQ>>>(
        bXn, bXnl, bWkT, bWkTl, nullptr, bk_h, bk_l, bk, nullptr, 1.0f,
        DD, DD, DD, HK, 0,0,0,0, 0,0,0);

    // 4. vT[b,h,k,s] = Wv^T(h) @ Xn^T(b) + bv[h,k]
    tgemm<6,1,true><<<dim3(SS/128, 1, 32), 512, SMEM_REQ>>>(
        bWvT, bWvTl, bXn, bXnl, nullptr, bvT_h, bvT_l, bv, nullptr, 1.0f,
        DD, DD, DD, SS,
        0, (long long)KK*DD, (long long)SS*DD, 0,
        (long long)HH*KK*SS, (long long)KK*SS, 0);

    // 5. kpT[b,h,m,s] = (elu(proj @ k^T)+1)/sqrt(M) * mask[token=col]
    tgemm<5,1,true><<<dim3(SS/128, MM/128, 32), 512, SMEM_REQ>>>(
        bproj, bprojl, bk_h, bk_l, nullptr, bkpT_h, bkpT_l, nullptr, mask, inv_sqrt_m,
        KK, KK, HK, SS,
        0, 0, (long long)SS*HK, KK,
        (long long)HH*MM*SS, (long long)MM*SS, 0);

    // 6. kv partials + reduce -> kvT
    tgemm<3,8,false><<<dim3(1, MM/128, 32*8), 512, SMEM_REQ>>>(
        bkpT_h, bkpT_l, bvT_h, bvT_l, part, nullptr, nullptr, nullptr, nullptr, 1.0f,
        SS, SS, SS, KK,
        (long long)HH*MM*SS, (long long)MM*SS, (long long)HH*KK*SS, (long long)KK*SS,
        2097152LL, 262144LL, 32768LL);
    reduce_kvT_kernel<<<dim3(32, 8), 256>>>(part, bkvT_h, bkvT_l);

    // 7. ksum from kpT
    ksum_kernel<<<dim3(32, 32), 256>>>(bkpT_h, bkpT_l, ks);

    // 8. fused qp + denom + attn
    fattn_kernel<<<dim3(1, SS/64, 32), 256, SMEM_FATTN>>>(
        bq_h, bq_l, bproj, bprojl, bkvT_h, bkvT_l, ks, bat_h, bat_l);

    // 9. ao = attn @ WoT + bo
    tgemm<0,1,false><<<dim3(1, BS/128, 1), 512, SMEM_REQ>>>(
        bat_h, bat_l, bWoT, bWoTl, ao, nullptr, nullptr, bo, nullptr, 1.0f,
        HK, HK, HK, DD, 0,0,0,0, 0,0,0);

    // 10+11. fused double LN
    ln_double_kernel<<<BS, 128>>>(Xn, ao, mask, ln2_g, ln2_b, fln0_g, fln0_b, btA_h, btA_l);

    // 12-14. FFN
    tgemm<1,1,false><<<dim3(1, BS/128, 1), 512, SMEM_REQ>>>(
        btA_h, btA_l, bfw0T, bfw0Tl, tB, nullptr, nullptr, f_b0, nullptr, 1.0f,
        DD, DD, DD, DD, 0,0,0,0, 0,0,0);
    ln_kernel<<<BS, 128>>>(tB, fln1_g, fln1_b, nullptr, btA_h, btA_l);
    tgemm<0,1,false><<<dim3(1, BS/128, 1), 512, SMEM_REQ>>>(
        btA_h, btA_l, bfw1T, bfw1Tl, out, nullptr, nullptr, f_b1, nullptr, 1.0f,
        DD, DD, DD, DD, 0,0,0,0, 0,0,0);
}

// round 11
// speedup vs baseline: 1.1763x; 1.1612x over previous
#include <cuda_runtime.h>
#include <cuda_fp16.h>
#include <math.h>
#include <stdint.h>

// Problem constants
#define BB 4
#define SS 4096
#define DD 128
#define HH 8
#define KK 128
#define MM 256

#define BS   (BB*SS)        // 16384
#define BSH  (BB*SS*HH)     // 131072
#define HK   (HH*KK)        // 1024
#define HM   (HH*MM)        // 2048

typedef __half hf;

// -------- scratch (static device globals) --------
__device__ float g_Xn  [BS*DD];
__device__ float g_part[2097152];              // kv split-K partials
__device__ float g_ks  [BB*HH*MM];
__device__ float g_ao  [BS*DD];
__device__ float g_tB  [BS*DD];

// fp16 hi/lo pairs (hi at [0], lo at [1])
__device__ hf b_Q   [2][BS*DD];
__device__ hf b_Xn  [2][BS*DD];
__device__ hf b_WqT [2][HK*DD];
__device__ hf b_WkT [2][HK*DD];
__device__ hf b_WvT [2][HK*DD];
__device__ hf b_WoT [2][DD*HK];
__device__ hf b_proj[2][MM*KK];
__device__ hf b_fw0T[2][DD*DD];
__device__ hf b_fw1T[2][DD*DD];
__device__ hf b_q   [2][BS*HK];
__device__ hf b_k   [2][BS*HK];
__device__ hf b_kpT [2][(size_t)BSH*MM];     // [b,h,m,s]
__device__ hf b_vT  [2][BS*HK];              // [b,h,k,s]
__device__ hf b_kvT [2][BB*HH*KK*MM];        // [b,h,k,m]
__device__ hf b_attn[2][(size_t)BS*HK];      // [b,s,h,k]
__device__ hf b_tA  [2][BS*DD];

// ================= asm helpers =================
__device__ __forceinline__ uint32_t smem_u32(const void* p) {
    uint32_t a;
    asm("{ .reg .u64 t; cvta.to.shared.u64 t, %1; cvt.u32.u64 %0, t; }" : "=r"(a) : "l"(p));
    return a;
}
#define CP_ASYNC16(dst, src) asm volatile("cp.async.cg.shared.global [%0], [%1], 16;" :: "r"(dst), "l"(__cvta_generic_to_global(src)))
#define CP_COMMIT()          asm volatile("cp.async.commit_group;")
#define CP_WAIT(n)           asm volatile("cp.async.wait_group %0;" :: "n"(n))

__device__ __forceinline__ void ldsm4(uint32_t* r, uint32_t a) {
    asm volatile("ldmatrix.sync.aligned.m8n8.x4.shared.b16 {%0,%1,%2,%3}, [%4];"
        : "=r"(r[0]), "=r"(r[1]), "=r"(r[2]), "=r"(r[3]) : "r"(a));
}
__device__ __forceinline__ void mma_f16(float* d, const uint32_t* a, const uint32_t* b) {
    asm volatile("mma.sync.aligned.m16n8k16.row.col.f32.f16.f16.f32 "
        "{%0,%1,%2,%3}, {%4,%5,%6,%7}, {%8,%9}, {%0,%1,%2,%3};"
        : "+f"(d[0]), "+f"(d[1]), "+f"(d[2]), "+f"(d[3])
        : "r"(a[0]), "r"(a[1]), "r"(a[2]), "r"(a[3]), "r"(b[0]), "r"(b[1]));
}
__device__ __forceinline__ void split_h(float v, hf& h, hf& l) {
    h = __float2half(v);
    l = __float2half(v - __half2float(h));
}
__device__ __forceinline__ void st_h2(hf* p, hf a, hf b) {
    *reinterpret_cast<__half2*>(p) = __halves2half2(a, b);
}

// ---------------- chunk-tile loader: [R rows x 64 c] fp16 -> swizzled smem ----------------
template<int R, int NTHR>
__device__ __forceinline__ void load_ct(uint32_t sU,
    const hf* __restrict__ G, int ld, int base0, int k0, int tid)
{
    #pragma unroll
    for (int i = 0; i < (R*8)/NTHR; i++) {
        int idx = tid + i*NTHR;
        int r = idx >> 3, c16 = idx & 7;
        const hf* src = G + (size_t)(base0 + r)*ld + k0 + c16*8;
        int off = r*128 + c16*16;
        int sw = off ^ ((off >> 3) & 0x70);
        CP_ASYNC16(sU + sw, src);
    }
}

// ================= fp16 2-term warp-MMA GEMM (512 thr, 3-stage) =================
// 128x128 CTA tile, K-tiles of 64, 16 warps 4(m)x4(n), warp tile 32m x 32n.
// A split hi+lo, B hi only: C += Ah*B + Al*B  (2 MMAs per term).
// EPI 0: (acc + bias[col]) * alpha
// EPI 1: elu(acc + bias[col])
// EPI 3: acc (split-K partial)
// EPI 5: (elu(acc)+1) * alpha * maskf[b*S+col]
// EPI 6: acc + bias[h*128+row]
template<int EPI, int NSPLIT, bool OUTB>
__global__ void __launch_bounds__(512) tgemm(
    const hf* __restrict__ Ah, const hf* __restrict__ Al,
    const hf* __restrict__ Bh,
    float* __restrict__ C, hf* __restrict__ Ch, hf* __restrict__ Cl,
    const float* __restrict__ bias, const int* __restrict__ mask,
    float alpha,
    int Kd, int lda, int ldb, int ldc,
    long long sAb, long long sAh2, long long sBb, long long sBh2,
    long long sCb, long long sCh2, long long sCs)
{
    extern __shared__ char dyn[];
    const int ASZ = 128*128;        // 16KB per half-tile
    const int BUFSZ = 3*ASZ;        // Ahi, Alo, Bhi = 48KB

    uint32_t dynU = smem_u32(dyn);
    uint32_t smU = (dynU + 1023u) & ~1023u;

    int tid = threadIdx.x;
    int lane = tid & 31, wid = tid >> 5;
    int wm = (wid & 3) * 32, wn = (wid >> 2) * 32;

    int z = blockIdx.z;
    int split = z % NSPLIT, bh = z / NSPLIT;
    int b = bh >> 3, h = bh & 7;
    Ah += (long long)b*sAb + (long long)h*sAh2;
    Al += (long long)b*sAb + (long long)h*sAh2;
    Bh += (long long)b*sBb + (long long)h*sBh2;
    long long coff = (long long)b*sCb + (long long)h*sCh2 + (long long)split*sCs;
    if (OUTB) { Ch += coff; Cl += coff; } else { C += coff; }
    int kchunk = Kd / NSPLIT;
    int kbeg = split * kchunk;
    int nk = kchunk / 64;
    int m0 = blockIdx.y * 128, n0 = blockIdx.x * 128;

    float acc[2][4][4] = {};

    auto copy_stage = [&](int st, int k0) {
        uint32_t dU = smU + st*BUFSZ;
        load_ct<128,512>(dU,         Ah, lda, m0, k0, tid);
        load_ct<128,512>(dU + ASZ,   Al, lda, m0, k0, tid);
        load_ct<128,512>(dU + 2*ASZ, Bh, ldb, n0, k0, tid);
    };

    copy_stage(0, kbeg);            CP_COMMIT();
    copy_stage(1, kbeg + 64);       CP_COMMIT();

    int rA = wm + (lane & 15);
    int cA = lane >> 4;
    int rB = wn + (lane & 7) + ((lane >> 4) & 1) * 8;
    int cB = (lane >> 3) & 1;

    for (int it = 0; it < nk; it++) {
        if (it < nk - 1) { CP_WAIT(1); } else { CP_WAIT(0); }
        __syncthreads();
        if (it + 2 < nk) {
            copy_stage((it + 2) % 3, kbeg + (it+2)*64);
            CP_COMMIT();
        }
        uint32_t aH = smU + (it % 3)*BUFSZ;
        uint32_t aL = aH + ASZ;
        uint32_t bH = aH + 2*ASZ;
        #pragma unroll
        for (int ks = 0; ks < 4; ks++) {
            uint32_t afh[2][4], afl[2][4], bfh[4][2];
            #pragma unroll
            for (int mi = 0; mi < 2; mi++) {
                int row = rA + mi*16;
                int sw = row*128 + (((ks*2 + cA) ^ (row & 7)) * 16);
                ldsm4(afh[mi], aH + sw);
                ldsm4(afl[mi], aL + sw);
            }
            #pragma unroll
            for (int nj = 0; nj < 2; nj++) {
                int row = rB + nj*16;
                int sw = row*128 + (((ks*2 + cB) ^ (row & 7)) * 16);
                ldsm4(&bfh[nj*2][0], bH + sw);
            }
            #pragma unroll
            for (int mi = 0; mi < 2; mi++)
                #pragma unroll
                for (int ni = 0; ni < 4; ni++) {
                    mma_f16(acc[mi][ni], afh[mi], bfh[ni]);
                    mma_f16(acc[mi][ni], afl[mi], bfh[ni]);
                }
        }
        __syncthreads();
    }

    // epilogue
    #pragma unroll
    for (int mi = 0; mi < 2; mi++) {
        int r0 = m0 + wm + mi*16 + (lane >> 2);
        int r1 = r0 + 8;
        float f0 = 1.0f, f1 = 1.0f;
        if (EPI == 6) {
            f0 = bias[(h << 7) + r0];
            f1 = bias[(h << 7) + r1];
        }
        #pragma unroll
        for (int ni = 0; ni < 4; ni++) {
            int c0 = n0 + wn + ni*8 + (lane & 3)*2;
            float d0 = acc[mi][ni][0], d1 = acc[mi][ni][1];
            float d2 = acc[mi][ni][2], d3 = acc[mi][ni][3];
            if (EPI == 0) {
                float b0 = bias ? bias[c0] : 0.0f, b1 = bias ? bias[c0+1] : 0.0f;
                d0 = (d0 + b0)*alpha; d1 = (d1 + b1)*alpha;
                d2 = (d2 + b0)*alpha; d3 = (d3 + b1)*alpha;
            } else if (EPI == 1) {
                float b0 = bias[c0], b1 = bias[c0+1];
                d0 += b0; d1 += b1; d2 += b0; d3 += b1;
                d0 = d0 > 0.0f ? d0 : expm1f(d0);
                d1 = d1 > 0.0f ? d1 : expm1f(d1);
                d2 = d2 > 0.0f ? d2 : expm1f(d2);
                d3 = d3 > 0.0f ? d3 : expm1f(d3);
            } else if (EPI == 5) {
                float m0f = (float)mask[b*SS + c0];
                float m1f = (float)mask[b*SS + c0 + 1];
                d0 = (d0 > 0.0f ? d0 + 1.0f : expf(d0)) * alpha * m0f;
                d1 = (d1 > 0.0f ? d1 + 1.0f : expf(d1)) * alpha * m1f;
                d2 = (d2 > 0.0f ? d2 + 1.0f : expf(d2)) * alpha * m0f;
                d3 = (d3 > 0.0f ? d3 + 1.0f : expf(d3)) * alpha * m1f;
            } else if (EPI == 6) {
                d0 += f0; d1 += f0; d2 += f1; d3 += f1;
            }
            if (OUTB) {
                hf h0, l0, h1, l1, h2, l2, h3, l3;
                split_h(d0, h0, l0); split_h(d1, h1, l1);
                split_h(d2, h2, l2); split_h(d3, h3, l3);
                st_h2(Ch + (size_t)r0*ldc + c0, h0, h1);
                st_h2(Cl + (size_t)r0*ldc + c0, l0, l1);
                st_h2(Ch + (size_t)r1*ldc + c0, h2, h3);
                st_h2(Cl + (size_t)r1*ldc + c0, l2, l3);
            } else {
                *reinterpret_cast<float2*>(C + (size_t)r0*ldc + c0) = make_float2(d0, d1);
                *reinterpret_cast<float2*>(C + (size_t)r1*ldc + c0) = make_float2(d2, d3);
            }
        }
    }
}

// ================= fused qp + denom + attn kernel (256 threads) =================
#define FA_QP_HI 0
#define FA_QP_LO 32768
#define FA_QT_HI 65536
#define FA_QT_LO 81920
#define FA_BBUF  98304
#define SMEM_FATTN (131072 + 1024)

__global__ void __launch_bounds__(256) fattn_kernel(
    const hf* __restrict__ qh, const hf* __restrict__ ql,
    const hf* __restrict__ projh,
    const hf* __restrict__ kvh,
    const float* __restrict__ ksum,
    hf* __restrict__ outh, hf* __restrict__ outl)
{
    extern __shared__ char dyn[];
    __shared__ float dn_smem[64];
    uint32_t dynU = smem_u32(dyn);
    uint32_t smU = (dynU + 1023u) & ~1023u;

    int tid = threadIdx.x;
    int lane = tid & 31, wid = tid >> 5;
    int ws = wid & 1, wn = wid >> 1;          // 2(s) x 4(n) warps; warp tile 32 x 32

    int bh = blockIdx.z;
    int b = bh >> 3, h = bh & 7;
    int s0 = blockIdx.y * 64;

    const hf* qhp = qh + ((size_t)(b*SS + s0))*HK + h*KK;
    const hf* qlp = ql + ((size_t)(b*SS + s0))*HK + h*KK;
    const hf* kvhp = kvh + (size_t)bh*KK*MM;
    const float* ksp = ksum + bh*MM;

    const float inv_sqrt_m = 0.0625f;

    // load q tile (64 rows x 128 k as 2 chunk-tiles, hi+lo)
    load_ct<64,256>(smU + FA_QT_HI,        qhp, HK, 0, 0,  tid);
    load_ct<64,256>(smU + FA_QT_HI + 8192, qhp, HK, 0, 64, tid);
    load_ct<64,256>(smU + FA_QT_LO,        qlp, HK, 0, 0,  tid);
    load_ct<64,256>(smU + FA_QT_LO + 8192, qlp, HK, 0, 64, tid);

    // B loader: it<4 -> proj[mh*128 rows, kt*64]; it>=4 -> kvT chunk it-4 (hi only)
    auto loadB = [&](int it) {
        uint32_t dU = smU + FA_BBUF + (it & 1)*16384;
        if (it < 4) {
            int mh = it >> 1, kt = it & 1;
            load_ct<128,256>(dU, projh, KK, mh*128, kt*64, tid);
        } else {
            int ch = it - 4;
            load_ct<128,256>(dU, kvhp, MM, 0, ch*64, tid);
        }
    };

    loadB(0); CP_COMMIT();
    loadB(1); CP_COMMIT();

    int rAl = ws*32 + (lane & 15);
    int cA  = lane >> 4;
    int rBl = wn*32 + (lane & 7) + ((lane >> 4) & 1) * 8;
    int cB  = (lane >> 3) & 1;

    float acc[2][4][4] = {};

    for (int it = 0; it < 8; it++) {
        if (it < 7) { CP_WAIT(1); } else { CP_WAIT(0); }
        __syncthreads();

        uint32_t aH, aL;
        if (it < 4) {
            int kt = it & 1;
            aH = smU + FA_QT_HI + kt*8192;
            aL = smU + FA_QT_LO + kt*8192;
        } else {
            int ch = it - 4;
            aH = smU + FA_QP_HI + ch*8192;
            aL = smU + FA_QP_LO + ch*8192;
        }
        uint32_t bH = smU + FA_BBUF + (it & 1)*16384;

        #pragma unroll
        for (int ks = 0; ks < 4; ks++) {
            uint32_t afh[2][4], afl[2][4], bfh[4][2];
            #pragma unroll
            for (int mi = 0; mi < 2; mi++) {
                int row = rAl + mi*16;
                int sw = row*128 + (((ks*2 + cA) ^ (row & 7)) * 16);
                ldsm4(afh[mi], aH + sw);
                ldsm4(afl[mi], aL + sw);
            }
            #pragma unroll
            for (int nj = 0; nj < 2; nj++) {
                int row = rBl + nj*16;
                int sw = row*128 + (((ks*2 + cB) ^ (row & 7)) * 16);
                ldsm4(&bfh[nj*2][0], bH + sw);
            }
            #pragma unroll
            for (int mi = 0; mi < 2; mi++)
                #pragma unroll
                for (int ni = 0; ni < 4; ni++) {
                    mma_f16(acc[mi][ni], afh[mi], bfh[ni]);
                    mma_f16(acc[mi][ni], afl[mi], bfh[ni]);
                }
        }

        // phase-1 epilogue: qp -> smem after both k-tiles of a half (it==1: mh0, it==3: mh1)
        if (it == 1 || it == 3) {
            int mh = it >> 1;
            char* base = dyn + (smU - dynU);
            #pragma unroll
            for (int mi = 0; mi < 2; mi++) {
                int r0 = ws*32 + mi*16 + (lane >> 2);
                int r1 = r0 + 8;
                #pragma unroll
                for (int ni = 0; ni < 4; ni++) {
                    int cl = wn*32 + ni*8 + (lane & 3)*2;
                    int mg = mh*128 + cl;
                    int chunk = mg >> 6, cin = mg & 63;
                    float d0 = acc[mi][ni][0], d1 = acc[mi][ni][1];
                    float d2 = acc[mi][ni][2], d3 = acc[mi][ni][3];
                    d0 = (d0 > 0.0f ? d0 + 1.0f : expf(d0)) * inv_sqrt_m;
                    d1 = (d1 > 0.0f ? d1 + 1.0f : expf(d1)) * inv_sqrt_m;
                    d2 = (d2 > 0.0f ? d2 + 1.0f : expf(d2)) * inv_sqrt_m;
                    d3 = (d3 > 0.0f ? d3 + 1.0f : expf(d3)) * inv_sqrt_m;
                    hf h0, l0, h1, l1, h2, l2, h3, l3;
                    split_h(d0, h0, l0); split_h(d1, h1, l1);
                    split_h(d2, h2, l2); split_h(d3, h3, l3);
                    int o0 = r0*128 + cin*2;  int sw0 = o0 ^ ((o0 >> 3) & 0x70);
                    int o1 = r1*128 + cin*2;  int sw1 = o1 ^ ((o1 >> 3) & 0x70);
                    st_h2(reinterpret_cast<hf*>(base + FA_QP_HI + chunk*8192 + sw0), h0, h1);
                    st_h2(reinterpret_cast<hf*>(base + FA_QP_LO + chunk*8192 + sw0), l0, l1);
                    st_h2(reinterpret_cast<hf*>(base + FA_QP_HI + chunk*8192 + sw1), h2, h3);
                    st_h2(reinterpret_cast<hf*>(base + FA_QP_LO + chunk*8192 + sw1), l2, l3);
                }
            }
            #pragma unroll
            for (int mi = 0; mi < 2; mi++)
                #pragma unroll
                for (int ni = 0; ni < 4; ni++)
                    #pragma unroll
                    for (int c = 0; c < 4; c++)
                        acc[mi][ni][c] = 0.0f;
        }

        __syncthreads();   // protects B-buffer reuse + QP visibility

        if (it == 3) {
            int row = tid >> 2, part = tid & 3;
            char* base = dyn + (smU - dynU);
            float s = 0.0f;
            for (int j = 0; j < 64; j++) {
                int o = row*128 + j*2;
                int sw = o ^ ((o >> 3) & 0x70);
                float hv = __half2float(*reinterpret_cast<hf*>(base + FA_QP_HI + part*8192 + sw));
                float lv = __half2float(*reinterpret_cast<hf*>(base + FA_QP_LO + part*8192 + sw));
                s += (hv + lv) * ksp[part*64 + j];
            }
            s += __shfl_down_sync(0xffffffffu, s, 1);
            s += __shfl_down_sync(0xffffffffu, s, 2);
            if (part == 0) dn_smem[row] = 1.0f / (s + 1e-6f);
            __syncthreads();
        }

        if (it + 2 < 8) { loadB(it + 2); CP_COMMIT(); }
    }

    // phase-2 epilogue: attn out with dn
    #pragma unroll
    for (int mi = 0; mi < 2; mi++) {
        int r0 = ws*32 + mi*16 + (lane >> 2);
        int r1 = r0 + 8;
        float f0 = dn_smem[r0], f1 = dn_smem[r1];
        #pragma unroll
        for (int ni = 0; ni < 4; ni++) {
            int ck = wn*32 + ni*8 + (lane & 3)*2;
            float d0 = acc[mi][ni][0]*f0, d1 = acc[mi][ni][1]*f0;
            float d2 = acc[mi][ni][2]*f1, d3 = acc[mi][ni][3]*f1;
            hf h0, l0, h1, l1, h2, l2, h3, l3;
            split_h(d0, h0, l0); split_h(d1, h1, l1);
            split_h(d2, h2, l2); split_h(d3, h3, l3);
            size_t a0 = ((size_t)(b*SS + s0 + r0))*HK + h*KK + ck;
            size_t a1 = ((size_t)(b*SS + s0 + r1))*HK + h*KK + ck;
            st_h2(outh + a0, h0, h1);
            st_h2(outl + a0, l0, l1);
            st_h2(outh + a1, h2, h3);
            st_h2(outl + a1, l2, l3);
        }
    }
}

// ---------------- converts ----------------
__global__ void conv_kernel(const float* __restrict__ src, hf* __restrict__ hi,
                            hf* __restrict__ lo, int n)
{
    int i = blockIdx.x*256 + threadIdx.x;
    if (i < n) { hf h, l; split_h(src[i], h, l); hi[i] = h; lo[i] = l; }
}
__global__ void convT3_kernel(const float* __restrict__ s0, const float* __restrict__ s1,
                              const float* __restrict__ s2,
                              hf* __restrict__ h0, hf* __restrict__ l0,
                              hf* __restrict__ h1, hf* __restrict__ l1,
                              hf* __restrict__ h2, hf* __restrict__ l2,
                              int R, int C)
{
    const float* src = blockIdx.y == 0 ? s0 : (blockIdx.y == 1 ? s1 : s2);
    hf* hi = blockIdx.y == 0 ? h0 : (blockIdx.y == 1 ? h1 : h2);
    hf* lo = blockIdx.y == 0 ? l0 : (blockIdx.y == 1 ? l1 : l2);
    if (src == nullptr) return;
    int i = blockIdx.x*256 + threadIdx.x;
    if (i < R*C) {
        int r = i / C, c = i % C;
        hf h, l; split_h(src[i], h, l);
        hi[(size_t)c*R + r] = h; lo[(size_t)c*R + r] = l;
    }
}
__global__ void convT_kernel(const float* __restrict__ src, hf* __restrict__ hi,
                             hf* __restrict__ lo, int R, int C)
{
    int i = blockIdx.x*256 + threadIdx.x;
    if (i < R*C) {
        int r = i / C, c = i % C;
        hf h, l; split_h(src[i], h, l);
        hi[(size_t)c*R + r] = h; lo[(size_t)c*R + r] = l;
    }
}

// ---------------- LayerNorm ----------------
__device__ __forceinline__ float block_ln(float x, int t, float* smv, float eps,
                                          const float* g, const float* b2)
{
    float s = x;
    #pragma unroll
    for (int o = 16; o; o >>= 1) s += __shfl_down_sync(0xffffffffu, s, o);
    if ((t & 31) == 0) smv[t >> 5] = s;
    __syncthreads();
    float mu = (smv[0] + smv[1] + smv[2] + smv[3]) * (1.0f/128.0f);
    float d = x - mu;
    float s2 = d * d;
    __syncthreads();
    #pragma unroll
    for (int o = 16; o; o >>= 1) s2 += __shfl_down_sync(0xffffffffu, s2, o);
    if ((t & 31) == 0) smv[t >> 5] = s2;
    __syncthreads();
    float var = (smv[0] + smv[1] + smv[2] + smv[3]) * (1.0f/128.0f);
    __syncthreads();
    return d * rsqrtf(var + eps) * g[t] + b2[t];
}

__global__ void ln_kernel(const float* __restrict__ in1,
                          const float* __restrict__ gamma, const float* __restrict__ beta,
                          float* __restrict__ outf, hf* __restrict__ outh, hf* __restrict__ outl)
{
    int row = blockIdx.x;
    int t = threadIdx.x;
    __shared__ float smv[4];
    float x = in1[(size_t)row*DD + t];
    float y = block_ln(x, t, smv, 1e-3f, gamma, beta);
    size_t idx = (size_t)row*DD + t;
    if (outf) outf[idx] = y;
    if (outh) { hf h, l; split_h(y, h, l); outh[idx] = h; outl[idx] = l; }
}

__global__ void ln_double_kernel(const float* __restrict__ Xn, const float* __restrict__ ao,
                                 const int* __restrict__ mask,
                                 const float* __restrict__ g2, const float* __restrict__ b2,
                                 const float* __restrict__ g0, const float* __restrict__ b0,
                                 hf* __restrict__ outh, hf* __restrict__ outl)
{
    int row = blockIdx.x;
    int t = threadIdx.x;
    __shared__ float smv[4];
    float mf = (float)mask[row];
    float x = Xn[(size_t)row*DD + t] + ao[(size_t)row*DD + t] * mf;
    float y1 = block_ln(x, t, smv, 1e-3f, g2, b2);
    float y2 = block_ln(y1, t, smv, 1e-3f, g0, b0);
    size_t idx = (size_t)row*DD + t;
    hf h, l; split_h(y2, h, l);
    outh[idx] = h; outl[idx] = l;
}

// ---------------- kv reduce + transpose ----------------
__global__ void reduce_kvT_kernel(const float* __restrict__ part,
                                  hf* __restrict__ hi, hf* __restrict__ lo)
{
    int bh = blockIdx.x;
    int tm = (blockIdx.y >> 1) * 64;
    int tk = (blockIdx.y & 1) * 64;
    __shared__ float t[64][65];
    const float* p = part + (size_t)bh*8*32768;
    int tid = threadIdx.x;
    #pragma unroll
    for (int i = 0; i < 16; i++) {
        int idx = tid + i*256;
        int r = idx >> 6, c = idx & 63;
        float s = 0.0f;
        #pragma unroll
        for (int sp = 0; sp < 8; sp++) s += p[sp*32768 + (tm+r)*128 + tk+c];
        t[c][r] = s;
    }
    __syncthreads();
    hf* H = hi + (size_t)bh*KK*MM;
    hf* L = lo + (size_t)bh*KK*MM;
    #pragma unroll
    for (int i = 0; i < 16; i++) {
        int idx = tid + i*256;
        int kk2 = idx >> 6, mm2 = idx & 63;
        float s = t[kk2][mm2];
        hf h, l; split_h(s, h, l);
        H[(size_t)(tk+kk2)*MM + tm+mm2] = h;
        L[(size_t)(tk+kk2)*MM + tm+mm2] = l;
    }
}

// ---------------- ksum from kpT ----------------
__global__ void ksum_kernel(const hf* __restrict__ kph, const hf* __restrict__ kpl,
                            float* __restrict__ ks)
{
    int bh = blockIdx.x;
    int wid = threadIdx.x >> 5, lane = threadIdx.x & 31;
    int m = blockIdx.y * 8 + wid;
    const hf* H = kph + ((size_t)bh*MM + m)*SS;
    const hf* L = kpl + ((size_t)bh*MM + m)*SS;
    float s = 0.0f;
    for (int i = lane; i < SS; i += 32)
        s += __half2float(H[i]) + __half2float(L[i]);
    #pragma unroll
    for (int o = 16; o; o >>= 1) s += __shfl_down_sync(0xffffffffu, s, o);
    if (lane == 0) ks[bh*MM + m] = s;
}

// ---------------- host-side launch ----------------
template<typename T>
static T* sym_addr(const void* sym)
{
    void* p = nullptr;
    cudaGetSymbolAddress(&p, sym);
    return (T*)p;
}

#define SMEM_REQ (3*3*128*128 + 1024)   // 148480

extern "C" void kernel_launch(void* const* d_in, const int* in_sizes, int n_in,
                              void* d_out, int out_size)
{
    (void)in_sizes; (void)n_in; (void)out_size;
    const float* Q      = (const float*)d_in[0];
    const float* X      = (const float*)d_in[1];
    const int*   mask   = (const int*)  d_in[2];
    const float* Wq     = (const float*)d_in[3];
    const float* bq     = (const float*)d_in[4];
    const float* Wk     = (const float*)d_in[5];
    const float* bk     = (const float*)d_in[6];
    const float* Wv     = (const float*)d_in[7];
    const float* bv     = (const float*)d_in[8];
    const float* Wo     = (const float*)d_in[9];
    const float* bo     = (const float*)d_in[10];
    const float* proj   = (const float*)d_in[11];
    const float* ln1_g  = (const float*)d_in[12];
    const float* ln1_b  = (const float*)d_in[13];
    const float* ln2_g  = (const float*)d_in[14];
    const float* ln2_b  = (const float*)d_in[15];
    const float* fln0_g = (const float*)d_in[16];
    const float* fln0_b = (const float*)d_in[17];
    const float* f_w0   = (const float*)d_in[18];
    const float* f_b0   = (const float*)d_in[19];
    const float* fln1_g = (const float*)d_in[20];
    const float* fln1_b = (const float*)d_in[21];
    const float* f_w1   = (const float*)d_in[22];
    const float* f_b1   = (const float*)d_in[23];
    float* out = (float*)d_out;

    float* Xn   = sym_addr<float>(g_Xn);
    float* part = sym_addr<float>(g_part);
    float* ks   = sym_addr<float>(g_ks);
    float* ao   = sym_addr<float>(g_ao);
    float* tB   = sym_addr<float>(g_tB);

    hf* bQ    = sym_addr<hf>(b_Q);      hf* bQl    = bQ    + (size_t)BS*DD;
    hf* bXn   = sym_addr<hf>(b_Xn);     hf* bXnl   = bXn   + (size_t)BS*DD;
    hf* bWqT  = sym_addr<hf>(b_WqT);    hf* bWqTl  = bWqT  + (size_t)HK*DD;
    hf* bWkT  = sym_addr<hf>(b_WkT);    hf* bWkTl  = bWkT  + (size_t)HK*DD;
    hf* bWvT  = sym_addr<hf>(b_WvT);    hf* bWvTl  = bWvT  + (size_t)HK*DD;
    hf* bWoT  = sym_addr<hf>(b_WoT);    hf* bWoTl  = bWoT  + (size_t)DD*HK;
    hf* bproj = sym_addr<hf>(b_proj);   hf* bprojl = bproj + (size_t)MM*KK;
    hf* bfw0T = sym_addr<hf>(b_fw0T);   hf* bfw0Tl = bfw0T + (size_t)DD*DD;
    hf* bfw1T = sym_addr<hf>(b_fw1T);   hf* bfw1Tl = bfw1T + (size_t)DD*DD;
    hf* bq_h  = sym_addr<hf>(b_q);      hf* bq_l   = bq_h  + (size_t)BS*HK;
    hf* bk_h  = sym_addr<hf>(b_k);      hf* bk_l   = bk_h  + (size_t)BS*HK;
    hf* bkpT_h= sym_addr<hf>(b_kpT);    hf* bkpT_l = bkpT_h+ (size_t)BSH*MM;
    hf* bvT_h = sym_addr<hf>(b_vT);     hf* bvT_l  = bvT_h + (size_t)BS*HK;
    hf* bkvT_h= sym_addr<hf>(b_kvT);    hf* bkvT_l = bkvT_h+ (size_t)BB*HH*KK*MM;
    hf* bat_h = sym_addr<hf>(b_attn);   hf* bat_l  = bat_h + (size_t)BS*HK;
    hf* btA_h = sym_addr<hf>(b_tA);     hf* btA_l  = btA_h + (size_t)BS*DD;

    const float scale_q    = 0.08838834764831845f;  // 1/sqrt(128)
    const float inv_sqrt_m = 0.0625f;               // 1/sqrt(256)

    cudaFuncSetAttribute(tgemm<0,1,true >, cudaFuncAttributeMaxDynamicSharedMemorySize, SMEM_REQ);
    cudaFuncSetAttribute(tgemm<5,1,true >, cudaFuncAttributeMaxDynamicSharedMemorySize, SMEM_REQ);
    cudaFuncSetAttribute(tgemm<6,1,true >, cudaFuncAttributeMaxDynamicSharedMemorySize, SMEM_REQ);
    cudaFuncSetAttribute(tgemm<3,8,false>, cudaFuncAttributeMaxDynamicSharedMemorySize, SMEM_REQ);
    cudaFuncSetAttribute(tgemm<0,1,false>, cudaFuncAttributeMaxDynamicSharedMemorySize, SMEM_REQ);
    cudaFuncSetAttribute(tgemm<1,1,false>, cudaFuncAttributeMaxDynamicSharedMemorySize, SMEM_REQ);
    cudaFuncSetAttribute(fattn_kernel, cudaFuncAttributeMaxDynamicSharedMemorySize, SMEM_FATTN);

    // 0. converts
    conv_kernel<<<(BS*DD + 255)/256, 256>>>(Q, bQ, bQl, BS*DD);
    conv_kernel<<<(MM*KK + 255)/256, 256>>>(proj, bproj, bprojl, MM*KK);
    convT3_kernel<<<dim3((DD*HK + 255)/256, 3), 256>>>(
        Wq, Wk, Wv, bWqT, bWqTl, bWkT, bWkTl, bWvT, bWvTl, DD, HK);
    convT_kernel<<<(HK*DD + 255)/256, 256>>>(Wo, bWoT, bWoTl, HK, DD);
    convT3_kernel<<<dim3((DD*DD + 255)/256, 3), 256>>>(
        f_w0, f_w1, nullptr, bfw0T, bfw0Tl, bfw1T, bfw1Tl, nullptr, nullptr, DD, DD);

    // 1. Xn = LN(X; ln1)
    ln_kernel<<<BS, 128>>>(X, ln1_g, ln1_b, Xn, bXn, bXnl);

    // 2-3. q, k projections -> fp16 hi/lo [BS, HK]   (A=input split, B=weight hi)
    tgemm<0,1,true><<<dim3(HK/128, BS/128, 1), 512, SMEM_REQ>>>(
        bQ, bQl, bWqT, nullptr, bq_h, bq_l, bq, nullptr, scale_q,
        DD, DD, DD, HK, 0,0,0,0, 0,0,0);
    tgemm<0,1,true><<<dim3(HK/128, BS/128, 1), 512, SMEM_REQ>>>(
        bXn, bXnl, bWkT, nullptr, bk_h, bk_l, bk, nullptr, 1.0f,
        DD, DD, DD, HK, 0,0,0,0, 0,0,0);

    // 4. vT[b,h,k,s] = Wv^T(h) @ Xn^T(b) + bv[h,k]   (A=weight split, B=Xn hi)
    tgemm<6,1,true><<<dim3(SS/128, 1, 32), 512, SMEM_REQ>>>(
        bWvT, bWvTl, bXn, nullptr, bvT_h, bvT_l, bv, nullptr, 1.0f,
        DD, DD, DD, SS,
        0, (long long)KK*DD, (long long)SS*DD, 0,
        (long long)HH*KK*SS, (long long)KK*SS, 0);

    // 5. kpT[b,h,m,s] = (elu(proj @ k^T)+1)/sqrt(M) * mask[token=col]
    tgemm<5,1,true><<<dim3(SS/128, MM/128, 32), 512, SMEM_REQ>>>(
        bproj, bprojl, bk_h, nullptr, bkpT_h, bkpT_l, nullptr, mask, inv_sqrt_m,
        KK, KK, HK, SS,
        0, 0, (long long)SS*HK, KK,
        (long long)HH*MM*SS, (long long)MM*SS, 0);

    // 6. kv partials + reduce -> kvT  (A=kpT split, B=vT hi)
    tgemm<3,8,false><<<dim3(1, MM/128, 32*8), 512, SMEM_REQ>>>(
        bkpT_h, bkpT_l, bvT_h, part, nullptr, nullptr, nullptr, nullptr, 1.0f,
        SS, SS, SS, KK,
        (long long)HH*MM*SS, (long long)MM*SS, (long long)HH*KK*SS, (long long)KK*SS,
        2097152LL, 262144LL, 32768LL);
    reduce_kvT_kernel<<<dim3(32, 8), 256>>>(part, bkvT_h, bkvT_l);

    // 7. ksum from kpT
    ksum_kernel<<<dim3(32, 32), 256>>>(bkpT_h, bkpT_l, ks);

    // 8. fused qp + denom + attn
    fattn_kernel<<<dim3(1, SS/64, 32), 256, SMEM_FATTN>>>(
        bq_h, bq_l, bproj, bkvT_h, ks, bat_h, bat_l);

    // 9. ao = attn @ WoT + bo
    tgemm<0,1,false><<<dim3(1, BS/128, 1), 512, SMEM_REQ>>>(
        bat_h, bat_l, bWoT, ao, nullptr, nullptr, bo, nullptr, 1.0f,
        HK, HK, HK, DD, 0,0,0,0, 0,0,0);

    // 10+11. fused double LN
    ln_double_kernel<<<BS, 128>>>(Xn, ao, mask, ln2_g, ln2_b, fln0_g, fln0_b, btA_h, btA_l);

    // 12-14. FFN
    tgemm<1,1,false><<<dim3(1, BS/128, 1), 512, SMEM_REQ>>>(
        btA_h, btA_l, bfw0T, tB, nullptr, nullptr, f_b0, nullptr, 1.0f,
        DD, DD, DD, DD, 0,0,0,0, 0,0,0);
    ln_kernel<<<BS, 128>>>(tB, fln1_g, fln1_b, nullptr, btA_h, btA_l);
    tgemm<0,1,false><<<dim3(1, BS/128, 1), 512, SMEM_REQ>>>(
        btA_h, btA_l, bfw1T, out, nullptr, nullptr, f_b1, nullptr, 1.0f,
        DD, DD, DD, DD, 0,0,0,0, 0,0,0);
}

// round 12
// speedup vs baseline: 1.8118x; 1.5402x over previous
#include <cuda_runtime.h>
#include <cuda_fp16.h>
#include <math.h>
#include <stdint.h>

// Problem constants
#define BB 4
#define SS 4096
#define DD 128
#define HH 8
#define KK 128
#define MM 256

#define BS   (BB*SS)        // 16384
#define BSH  (BB*SS*HH)     // 131072
#define HK   (HH*KK)        // 1024
#define HM   (HH*MM)        // 2048

typedef __half hf;

// -------- scratch (static device globals) --------
__device__ float g_Xn  [BS*DD];
__device__ float g_part[2097152];              // kv split-K partials
__device__ float g_ks  [BB*HH*MM];
__device__ float g_ao  [BS*DD];
__device__ float g_tB  [BS*DD];

// fp16 buffers (single precision level now)
__device__ hf b_Q   [BS*DD];
__device__ hf b_Xn  [BS*DD];
__device__ hf b_WqT [HK*DD];
__device__ hf b_WkT [HK*DD];
__device__ hf b_WvT [HK*DD];
__device__ hf b_WoT [DD*HK];
__device__ hf b_proj[MM*KK];
__device__ hf b_fw0T[DD*DD];
__device__ hf b_fw1T[DD*DD];
__device__ hf b_q   [BS*HK];
__device__ hf b_k   [BS*HK];
__device__ hf b_kpT [(size_t)BSH*MM];     // [b,h,m,s]
__device__ hf b_vT  [BS*HK];              // [b,h,k,s]
__device__ hf b_kvT [BB*HH*KK*MM];        // [b,h,k,m]
__device__ hf b_attn[(size_t)BS*HK];      // [b,s,h,k]
__device__ hf b_tA  [BS*DD];

// ================= asm helpers =================
__device__ __forceinline__ uint32_t smem_u32(const void* p) {
    uint32_t a;
    asm("{ .reg .u64 t; cvta.to.shared.u64 t, %1; cvt.u32.u64 %0, t; }" : "=r"(a) : "l"(p));
    return a;
}
#define CP_ASYNC16(dst, src) asm volatile("cp.async.cg.shared.global [%0], [%1], 16;" :: "r"(dst), "l"(__cvta_generic_to_global(src)))
#define CP_COMMIT()          asm volatile("cp.async.commit_group;")
#define CP_WAIT(n)           asm volatile("cp.async.wait_group %0;" :: "n"(n))

__device__ __forceinline__ void ldsm4(uint32_t* r, uint32_t a) {
    asm volatile("ldmatrix.sync.aligned.m8n8.x4.shared.b16 {%0,%1,%2,%3}, [%4];"
        : "=r"(r[0]), "=r"(r[1]), "=r"(r[2]), "=r"(r[3]) : "r"(a));
}
__device__ __forceinline__ void mma_f16(float* d, const uint32_t* a, const uint32_t* b) {
    asm volatile("mma.sync.aligned.m16n8k16.row.col.f32.f16.f16.f32 "
        "{%0,%1,%2,%3}, {%4,%5,%6,%7}, {%8,%9}, {%0,%1,%2,%3};"
        : "+f"(d[0]), "+f"(d[1]), "+f"(d[2]), "+f"(d[3])
        : "r"(a[0]), "r"(a[1]), "r"(a[2]), "r"(a[3]), "r"(b[0]), "r"(b[1]));
}
__device__ __forceinline__ void st_h2(hf* p, float a, float b) {
    *reinterpret_cast<__half2*>(p) = __halves2half2(__float2half(a), __float2half(b));
}

// ---------------- chunk-tile loader: [R rows x 64 c] fp16 -> swizzled smem ----------------
template<int R, int NTHR>
__device__ __forceinline__ void load_ct(uint32_t sU,
    const hf* __restrict__ G, int ld, int base0, int k0, int tid)
{
    #pragma unroll
    for (int i = 0; i < (R*8)/NTHR; i++) {
        int idx = tid + i*NTHR;
        int r = idx >> 3, c16 = idx & 7;
        const hf* src = G + (size_t)(base0 + r)*ld + k0 + c16*8;
        int off = r*128 + c16*16;
        int sw = off ^ ((off >> 3) & 0x70);
        CP_ASYNC16(sU + sw, src);
    }
}

// ================= fp16 warp-MMA GEMM (512 thr, 3-stage, 1 MMA/term) =================
// 128x128 CTA tile, K-tiles of 64, 16 warps 4(m)x4(n), warp tile 32m x 32n.
// EPI 0: (acc + bias[col]) * alpha
// EPI 1: elu(acc + bias[col])
// EPI 3: acc (split-K partial)
// EPI 5: (elu(acc)+1) * alpha * maskf[b*S+col]
// EPI 6: acc + bias[h*128+row]
template<int EPI, int NSPLIT, bool OUTB>
__global__ void __launch_bounds__(512) tgemm(
    const hf* __restrict__ Ah, const hf* __restrict__ Bh,
    float* __restrict__ C, hf* __restrict__ Ch,
    const float* __restrict__ bias, const int* __restrict__ mask,
    float alpha,
    int Kd, int lda, int ldb, int ldc,
    long long sAb, long long sAh2, long long sBb, long long sBh2,
    long long sCb, long long sCh2, long long sCs)
{
    extern __shared__ char dyn[];
    const int ASZ = 128*128;        // 16KB per tile
    const int BUFSZ = 2*ASZ;        // A, B = 32KB

    uint32_t dynU = smem_u32(dyn);
    uint32_t smU = (dynU + 1023u) & ~1023u;

    int tid = threadIdx.x;
    int lane = tid & 31, wid = tid >> 5;
    int wm = (wid & 3) * 32, wn = (wid >> 2) * 32;

    int z = blockIdx.z;
    int split = z % NSPLIT, bh = z / NSPLIT;
    int b = bh >> 3, h = bh & 7;
    Ah += (long long)b*sAb + (long long)h*sAh2;
    Bh += (long long)b*sBb + (long long)h*sBh2;
    long long coff = (long long)b*sCb + (long long)h*sCh2 + (long long)split*sCs;
    if (OUTB) { Ch += coff; } else { C += coff; }
    int kchunk = Kd / NSPLIT;
    int kbeg = split * kchunk;
    int nk = kchunk / 64;
    int m0 = blockIdx.y * 128, n0 = blockIdx.x * 128;

    float acc[2][4][4] = {};

    auto copy_stage = [&](int st, int k0) {
        uint32_t dU = smU + st*BUFSZ;
        load_ct<128,512>(dU,       Ah, lda, m0, k0, tid);
        load_ct<128,512>(dU + ASZ, Bh, ldb, n0, k0, tid);
    };

    copy_stage(0, kbeg);            CP_COMMIT();
    copy_stage(1, kbeg + 64);       CP_COMMIT();

    int rA = wm + (lane & 15);
    int cA = lane >> 4;
    int rB = wn + (lane & 7) + ((lane >> 4) & 1) * 8;
    int cB = (lane >> 3) & 1;

    for (int it = 0; it < nk; it++) {
        if (it < nk - 1) { CP_WAIT(1); } else { CP_WAIT(0); }
        __syncthreads();
        if (it + 2 < nk) {
            copy_stage((it + 2) % 3, kbeg + (it+2)*64);
            CP_COMMIT();
        }
        uint32_t aH = smU + (it % 3)*BUFSZ;
        uint32_t bH = aH + ASZ;
        #pragma unroll
        for (int ks = 0; ks < 4; ks++) {
            uint32_t afh[2][4], bfh[4][2];
            #pragma unroll
            for (int mi = 0; mi < 2; mi++) {
                int row = rA + mi*16;
                int sw = row*128 + (((ks*2 + cA) ^ (row & 7)) * 16);
                ldsm4(afh[mi], aH + sw);
            }
            #pragma unroll
            for (int nj = 0; nj < 2; nj++) {
                int row = rB + nj*16;
                int sw = row*128 + (((ks*2 + cB) ^ (row & 7)) * 16);
                ldsm4(&bfh[nj*2][0], bH + sw);
            }
            #pragma unroll
            for (int mi = 0; mi < 2; mi++)
                #pragma unroll
                for (int ni = 0; ni < 4; ni++)
                    mma_f16(acc[mi][ni], afh[mi], bfh[ni]);
        }
        __syncthreads();
    }

    // epilogue
    #pragma unroll
    for (int mi = 0; mi < 2; mi++) {
        int r0 = m0 + wm + mi*16 + (lane >> 2);
        int r1 = r0 + 8;
        float f0 = 1.0f, f1 = 1.0f;
        if (EPI == 6) {
            f0 = bias[(h << 7) + r0];
            f1 = bias[(h << 7) + r1];
        }
        #pragma unroll
        for (int ni = 0; ni < 4; ni++) {
            int c0 = n0 + wn + ni*8 + (lane & 3)*2;
            float d0 = acc[mi][ni][0], d1 = acc[mi][ni][1];
            float d2 = acc[mi][ni][2], d3 = acc[mi][ni][3];
            if (EPI == 0) {
                float b0 = bias ? bias[c0] : 0.0f, b1 = bias ? bias[c0+1] : 0.0f;
                d0 = (d0 + b0)*alpha; d1 = (d1 + b1)*alpha;
                d2 = (d2 + b0)*alpha; d3 = (d3 + b1)*alpha;
            } else if (EPI == 1) {
                float b0 = bias[c0], b1 = bias[c0+1];
                d0 += b0; d1 += b1; d2 += b0; d3 += b1;
                d0 = d0 > 0.0f ? d0 : expm1f(d0);
                d1 = d1 > 0.0f ? d1 : expm1f(d1);
                d2 = d2 > 0.0f ? d2 : expm1f(d2);
                d3 = d3 > 0.0f ? d3 : expm1f(d3);
            } else if (EPI == 5) {
                float m0f = (float)mask[b*SS + c0];
                float m1f = (float)mask[b*SS + c0 + 1];
                d0 = (d0 > 0.0f ? d0 + 1.0f : expf(d0)) * alpha * m0f;
                d1 = (d1 > 0.0f ? d1 + 1.0f : expf(d1)) * alpha * m1f;
                d2 = (d2 > 0.0f ? d2 + 1.0f : expf(d2)) * alpha * m0f;
                d3 = (d3 > 0.0f ? d3 + 1.0f : expf(d3)) * alpha * m1f;
            } else if (EPI == 6) {
                d0 += f0; d1 += f0; d2 += f1; d3 += f1;
            }
            if (OUTB) {
                st_h2(Ch + (size_t)r0*ldc + c0, d0, d1);
                st_h2(Ch + (size_t)r1*ldc + c0, d2, d3);
            } else {
                *reinterpret_cast<float2*>(C + (size_t)r0*ldc + c0) = make_float2(d0, d1);
                *reinterpret_cast<float2*>(C + (size_t)r1*ldc + c0) = make_float2(d2, d3);
            }
        }
    }
}

// ================= fused qp + denom + attn kernel (256 threads) =================
// smem: QP (hi) 0..32K, QT 32K..48K, BBUF 48K + st*16K. total 80KB.
#define FA_QP   0
#define FA_QT   32768
#define FA_BBUF 49152
#define SMEM_FATTN (81920 + 1024)

__global__ void __launch_bounds__(256) fattn_kernel(
    const hf* __restrict__ qh,
    const hf* __restrict__ projh,
    const hf* __restrict__ kvh,
    const float* __restrict__ ksum,
    hf* __restrict__ outh)
{
    extern __shared__ char dyn[];
    __shared__ float dn_smem[64];
    uint32_t dynU = smem_u32(dyn);
    uint32_t smU = (dynU + 1023u) & ~1023u;

    int tid = threadIdx.x;
    int lane = tid & 31, wid = tid >> 5;
    int ws = wid & 1, wn = wid >> 1;          // 2(s) x 4(n) warps; warp tile 32 x 32

    int bh = blockIdx.z;
    int b = bh >> 3, h = bh & 7;
    int s0 = blockIdx.y * 64;

    const hf* qhp = qh + ((size_t)(b*SS + s0))*HK + h*KK;
    const hf* kvhp = kvh + (size_t)bh*KK*MM;
    const float* ksp = ksum + bh*MM;

    const float inv_sqrt_m = 0.0625f;

    // load q tile (64 rows x 128 k as 2 chunk-tiles)
    load_ct<64,256>(smU + FA_QT,        qhp, HK, 0, 0,  tid);
    load_ct<64,256>(smU + FA_QT + 8192, qhp, HK, 0, 64, tid);

    auto loadB = [&](int it) {
        uint32_t dU = smU + FA_BBUF + (it & 1)*16384;
        if (it < 4) {
            int mh = it >> 1, kt = it & 1;
            load_ct<128,256>(dU, projh, KK, mh*128, kt*64, tid);
        } else {
            int ch = it - 4;
            load_ct<128,256>(dU, kvhp, MM, 0, ch*64, tid);
        }
    };

    loadB(0); CP_COMMIT();
    loadB(1); CP_COMMIT();

    int rAl = ws*32 + (lane & 15);
    int cA  = lane >> 4;
    int rBl = wn*32 + (lane & 7) + ((lane >> 4) & 1) * 8;
    int cB  = (lane >> 3) & 1;

    float acc[2][4][4] = {};

    for (int it = 0; it < 8; it++) {
        if (it < 7) { CP_WAIT(1); } else { CP_WAIT(0); }
        __syncthreads();

        uint32_t aH;
        if (it < 4) {
            int kt = it & 1;
            aH = smU + FA_QT + kt*8192;
        } else {
            int ch = it - 4;
            aH = smU + FA_QP + ch*8192;
        }
        uint32_t bH = smU + FA_BBUF + (it & 1)*16384;

        #pragma unroll
        for (int ks = 0; ks < 4; ks++) {
            uint32_t afh[2][4], bfh[4][2];
            #pragma unroll
            for (int mi = 0; mi < 2; mi++) {
                int row = rAl + mi*16;
                int sw = row*128 + (((ks*2 + cA) ^ (row & 7)) * 16);
                ldsm4(afh[mi], aH + sw);
            }
            #pragma unroll
            for (int nj = 0; nj < 2; nj++) {
                int row = rBl + nj*16;
                int sw = row*128 + (((ks*2 + cB) ^ (row & 7)) * 16);
                ldsm4(&bfh[nj*2][0], bH + sw);
            }
            #pragma unroll
            for (int mi = 0; mi < 2; mi++)
                #pragma unroll
                for (int ni = 0; ni < 4; ni++)
                    mma_f16(acc[mi][ni], afh[mi], bfh[ni]);
        }

        // phase-1 epilogue: qp -> smem (it==1: mh0, it==3: mh1)
        if (it == 1 || it == 3) {
            int mh = it >> 1;
            char* base = dyn + (smU - dynU);
            #pragma unroll
            for (int mi = 0; mi < 2; mi++) {
                int r0 = ws*32 + mi*16 + (lane >> 2);
                int r1 = r0 + 8;
                #pragma unroll
                for (int ni = 0; ni < 4; ni++) {
                    int cl = wn*32 + ni*8 + (lane & 3)*2;
                    int mg = mh*128 + cl;
                    int chunk = mg >> 6, cin = mg & 63;
                    float d0 = acc[mi][ni][0], d1 = acc[mi][ni][1];
                    float d2 = acc[mi][ni][2], d3 = acc[mi][ni][3];
                    d0 = (d0 > 0.0f ? d0 + 1.0f : expf(d0)) * inv_sqrt_m;
                    d1 = (d1 > 0.0f ? d1 + 1.0f : expf(d1)) * inv_sqrt_m;
                    d2 = (d2 > 0.0f ? d2 + 1.0f : expf(d2)) * inv_sqrt_m;
                    d3 = (d3 > 0.0f ? d3 + 1.0f : expf(d3)) * inv_sqrt_m;
                    int o0 = r0*128 + cin*2;  int sw0 = o0 ^ ((o0 >> 3) & 0x70);
                    int o1 = r1*128 + cin*2;  int sw1 = o1 ^ ((o1 >> 3) & 0x70);
                    st_h2(reinterpret_cast<hf*>(base + FA_QP + chunk*8192 + sw0), d0, d1);
                    st_h2(reinterpret_cast<hf*>(base + FA_QP + chunk*8192 + sw1), d2, d3);
                }
            }
            #pragma unroll
            for (int mi = 0; mi < 2; mi++)
                #pragma unroll
                for (int ni = 0; ni < 4; ni++)
                    #pragma unroll
                    for (int c = 0; c < 4; c++)
                        acc[mi][ni][c] = 0.0f;
        }

        __syncthreads();   // protects B-buffer reuse + QP visibility

        if (it == 3) {
            int row = tid >> 2, part = tid & 3;
            char* base = dyn + (smU - dynU);
            float s = 0.0f;
            for (int j = 0; j < 64; j++) {
                int o = row*128 + j*2;
                int sw = o ^ ((o >> 3) & 0x70);
                float hv = __half2float(*reinterpret_cast<hf*>(base + FA_QP + part*8192 + sw));
                s += hv * ksp[part*64 + j];
            }
            s += __shfl_down_sync(0xffffffffu, s, 1);
            s += __shfl_down_sync(0xffffffffu, s, 2);
            if (part == 0) dn_smem[row] = 1.0f / (s + 1e-6f);
            __syncthreads();
        }

        if (it + 2 < 8) { loadB(it + 2); CP_COMMIT(); }
    }

    // phase-2 epilogue
    #pragma unroll
    for (int mi = 0; mi < 2; mi++) {
        int r0 = ws*32 + mi*16 + (lane >> 2);
        int r1 = r0 + 8;
        float f0 = dn_smem[r0], f1 = dn_smem[r1];
        #pragma unroll
        for (int ni = 0; ni < 4; ni++) {
            int ck = wn*32 + ni*8 + (lane & 3)*2;
            size_t a0 = ((size_t)(b*SS + s0 + r0))*HK + h*KK + ck;
            size_t a1 = ((size_t)(b*SS + s0 + r1))*HK + h*KK + ck;
            st_h2(outh + a0, acc[mi][ni][0]*f0, acc[mi][ni][1]*f0);
            st_h2(outh + a1, acc[mi][ni][2]*f1, acc[mi][ni][3]*f1);
        }
    }
}

// ---------------- converts ----------------
__global__ void conv_kernel(const float* __restrict__ src, hf* __restrict__ hi, int n)
{
    int i = blockIdx.x*256 + threadIdx.x;
    if (i < n) hi[i] = __float2half(src[i]);
}
__global__ void convT3_kernel(const float* __restrict__ s0, const float* __restrict__ s1,
                              const float* __restrict__ s2,
                              hf* __restrict__ h0, hf* __restrict__ h1, hf* __restrict__ h2,
                              int R, int C)
{
    const float* src = blockIdx.y == 0 ? s0 : (blockIdx.y == 1 ? s1 : s2);
    hf* hi = blockIdx.y == 0 ? h0 : (blockIdx.y == 1 ? h1 : h2);
    if (src == nullptr) return;
    int i = blockIdx.x*256 + threadIdx.x;
    if (i < R*C) {
        int r = i / C, c = i % C;
        hi[(size_t)c*R + r] = __float2half(src[i]);
    }
}
__global__ void convT_kernel(const float* __restrict__ src, hf* __restrict__ hi, int R, int C)
{
    int i = blockIdx.x*256 + threadIdx.x;
    if (i < R*C) {
        int r = i / C, c = i % C;
        hi[(size_t)c*R + r] = __float2half(src[i]);
    }
}

// ---------------- LayerNorm ----------------
__device__ __forceinline__ float block_ln(float x, int t, float* smv, float eps,
                                          const float* g, const float* b2)
{
    float s = x;
    #pragma unroll
    for (int o = 16; o; o >>= 1) s += __shfl_down_sync(0xffffffffu, s, o);
    if ((t & 31) == 0) smv[t >> 5] = s;
    __syncthreads();
    float mu = (smv[0] + smv[1] + smv[2] + smv[3]) * (1.0f/128.0f);
    float d = x - mu;
    float s2 = d * d;
    __syncthreads();
    #pragma unroll
    for (int o = 16; o; o >>= 1) s2 += __shfl_down_sync(0xffffffffu, s2, o);
    if ((t & 31) == 0) smv[t >> 5] = s2;
    __syncthreads();
    float var = (smv[0] + smv[1] + smv[2] + smv[3]) * (1.0f/128.0f);
    __syncthreads();
    return d * rsqrtf(var + eps) * g[t] + b2[t];
}

__global__ void ln_kernel(const float* __restrict__ in1,
                          const float* __restrict__ gamma, const float* __restrict__ beta,
                          float* __restrict__ outf, hf* __restrict__ outh)
{
    int row = blockIdx.x;
    int t = threadIdx.x;
    __shared__ float smv[4];
    float x = in1[(size_t)row*DD + t];
    float y = block_ln(x, t, smv, 1e-3f, gamma, beta);
    size_t idx = (size_t)row*DD + t;
    if (outf) outf[idx] = y;
    if (outh) outh[idx] = __float2half(y);
}

__global__ void ln_double_kernel(const float* __restrict__ Xn, const float* __restrict__ ao,
                                 const int* __restrict__ mask,
                                 const float* __restrict__ g2, const float* __restrict__ b2,
                                 const float* __restrict__ g0, const float* __restrict__ b0,
                                 hf* __restrict__ outh)
{
    int row = blockIdx.x;
    int t = threadIdx.x;
    __shared__ float smv[4];
    float mf = (float)mask[row];
    float x = Xn[(size_t)row*DD + t] + ao[(size_t)row*DD + t] * mf;
    float y1 = block_ln(x, t, smv, 1e-3f, g2, b2);
    float y2 = block_ln(y1, t, smv, 1e-3f, g0, b0);
    outh[(size_t)row*DD + t] = __float2half(y2);
}

// ---------------- kv reduce + transpose ----------------
__global__ void reduce_kvT_kernel(const float* __restrict__ part, hf* __restrict__ hi)
{
    int bh = blockIdx.x;
    int tm = (blockIdx.y >> 1) * 64;
    int tk = (blockIdx.y & 1) * 64;
    __shared__ float t[64][65];
    const float* p = part + (size_t)bh*8*32768;
    int tid = threadIdx.x;
    #pragma unroll
    for (int i = 0; i < 16; i++) {
        int idx = tid + i*256;
        int r = idx >> 6, c = idx & 63;
        float s = 0.0f;
        #pragma unroll
        for (int sp = 0; sp < 8; sp++) s += p[sp*32768 + (tm+r)*128 + tk+c];
        t[c][r] = s;
    }
    __syncthreads();
    hf* H = hi + (size_t)bh*KK*MM;
    #pragma unroll
    for (int i = 0; i < 16; i++) {
        int idx = tid + i*256;
        int kk2 = idx >> 6, mm2 = idx & 63;
        H[(size_t)(tk+kk2)*MM + tm+mm2] = __float2half(t[kk2][mm2]);
    }
}

// ---------------- ksum from kpT ----------------
__global__ void ksum_kernel(const hf* __restrict__ kph, float* __restrict__ ks)
{
    int bh = blockIdx.x;
    int wid = threadIdx.x >> 5, lane = threadIdx.x & 31;
    int m = blockIdx.y * 8 + wid;
    const hf* H = kph + ((size_t)bh*MM + m)*SS;
    float s = 0.0f;
    for (int i = lane; i < SS; i += 32)
        s += __half2float(H[i]);
    #pragma unroll
    for (int o = 16; o; o >>= 1) s += __shfl_down_sync(0xffffffffu, s, o);
    if (lane == 0) ks[bh*MM + m] = s;
}

// ---------------- host-side launch ----------------
template<typename T>
static T* sym_addr(const void* sym)
{
    void* p = nullptr;
    cudaGetSymbolAddress(&p, sym);
    return (T*)p;
}

#define SMEM_REQ (3*2*128*128 + 1024)   // 99328

extern "C" void kernel_launch(void* const* d_in, const int* in_sizes, int n_in,
                              void* d_out, int out_size)
{
    (void)in_sizes; (void)n_in; (void)out_size;
    const float* Q      = (const float*)d_in[0];
    const float* X      = (const float*)d_in[1];
    const int*   mask   = (const int*)  d_in[2];
    const float* Wq     = (const float*)d_in[3];
    const float* bq     = (const float*)d_in[4];
    const float* Wk     = (const float*)d_in[5];
    const float* bk     = (const float*)d_in[6];
    const float* Wv     = (const float*)d_in[7];
    const float* bv     = (const float*)d_in[8];
    const float* Wo     = (const float*)d_in[9];
    const float* bo     = (const float*)d_in[10];
    const float* proj   = (const float*)d_in[11];
    const float* ln1_g  = (const float*)d_in[12];
    const float* ln1_b  = (const float*)d_in[13];
    const float* ln2_g  = (const float*)d_in[14];
    const float* ln2_b  = (const float*)d_in[15];
    const float* fln0_g = (const float*)d_in[16];
    const float* fln0_b = (const float*)d_in[17];
    const float* f_w0   = (const float*)d_in[18];
    const float* f_b0   = (const float*)d_in[19];
    const float* fln1_g = (const float*)d_in[20];
    const float* fln1_b = (const float*)d_in[21];
    const float* f_w1   = (const float*)d_in[22];
    const float* f_b1   = (const float*)d_in[23];
    float* out = (float*)d_out;

    float* Xn   = sym_addr<float>(g_Xn);
    float* part = sym_addr<float>(g_part);
    float* ks   = sym_addr<float>(g_ks);
    float* ao   = sym_addr<float>(g_ao);
    float* tB   = sym_addr<float>(g_tB);

    hf* bQ    = sym_addr<hf>(b_Q);
    hf* bXn   = sym_addr<hf>(b_Xn);
    hf* bWqT  = sym_addr<hf>(b_WqT);
    hf* bWkT  = sym_addr<hf>(b_WkT);
    hf* bWvT  = sym_addr<hf>(b_WvT);
    hf* bWoT  = sym_addr<hf>(b_WoT);
    hf* bproj = sym_addr<hf>(b_proj);
    hf* bfw0T = sym_addr<hf>(b_fw0T);
    hf* bfw1T = sym_addr<hf>(b_fw1T);
    hf* bq_h  = sym_addr<hf>(b_q);
    hf* bk_h  = sym_addr<hf>(b_k);
    hf* bkpT_h= sym_addr<hf>(b_kpT);
    hf* bvT_h = sym_addr<hf>(b_vT);
    hf* bkvT_h= sym_addr<hf>(b_kvT);
    hf* bat_h = sym_addr<hf>(b_attn);
    hf* btA_h = sym_addr<hf>(b_tA);

    const float scale_q    = 0.08838834764831845f;  // 1/sqrt(128)
    const float inv_sqrt_m = 0.0625f;               // 1/sqrt(256)

    cudaFuncSetAttribute(tgemm<0,1,true >, cudaFuncAttributeMaxDynamicSharedMemorySize, SMEM_REQ);
    cudaFuncSetAttribute(tgemm<5,1,true >, cudaFuncAttributeMaxDynamicSharedMemorySize, SMEM_REQ);
    cudaFuncSetAttribute(tgemm<6,1,true >, cudaFuncAttributeMaxDynamicSharedMemorySize, SMEM_REQ);
    cudaFuncSetAttribute(tgemm<3,8,false>, cudaFuncAttributeMaxDynamicSharedMemorySize, SMEM_REQ);
    cudaFuncSetAttribute(tgemm<0,1,false>, cudaFuncAttributeMaxDynamicSharedMemorySize, SMEM_REQ);
    cudaFuncSetAttribute(tgemm<1,1,false>, cudaFuncAttributeMaxDynamicSharedMemorySize, SMEM_REQ);
    cudaFuncSetAttribute(fattn_kernel, cudaFuncAttributeMaxDynamicSharedMemorySize, SMEM_FATTN);

    // 0. converts
    conv_kernel<<<(BS*DD + 255)/256, 256>>>(Q, bQ, BS*DD);
    conv_kernel<<<(MM*KK + 255)/256, 256>>>(proj, bproj, MM*KK);
    convT3_kernel<<<dim3((DD*HK + 255)/256, 3), 256>>>(
        Wq, Wk, Wv, bWqT, bWkT, bWvT, DD, HK);
    convT_kernel<<<(HK*DD + 255)/256, 256>>>(Wo, bWoT, HK, DD);
    convT3_kernel<<<dim3((DD*DD + 255)/256, 3), 256>>>(
        f_w0, f_w1, nullptr, bfw0T, bfw1T, nullptr, DD, DD);

    // 1. Xn = LN(X; ln1)
    ln_kernel<<<BS, 128>>>(X, ln1_g, ln1_b, Xn, bXn);

    // 2-3. q, k projections -> fp16 [BS, HK]
    tgemm<0,1,true><<<dim3(HK/128, BS/128, 1), 512, SMEM_REQ>>>(
        bQ, bWqT, nullptr, bq_h, bq, nullptr, scale_q,
        DD, DD, DD, HK, 0,0,0,0, 0,0,0);
    tgemm<0,1,true><<<dim3(HK/128, BS/128, 1), 512, SMEM_REQ>>>(
        bXn, bWkT, nullptr, bk_h, bk, nullptr, 1.0f,
        DD, DD, DD, HK, 0,0,0,0, 0,0,0);

    // 4. vT[b,h,k,s] = Wv^T(h) @ Xn^T(b) + bv[h,k]
    tgemm<6,1,true><<<dim3(SS/128, 1, 32), 512, SMEM_REQ>>>(
        bWvT, bXn, nullptr, bvT_h, bv, nullptr, 1.0f,
        DD, DD, DD, SS,
        0, (long long)KK*DD, (long long)SS*DD, 0,
        (long long)HH*KK*SS, (long long)KK*SS, 0);

    // 5. kpT[b,h,m,s] = (elu(proj @ k^T)+1)/sqrt(M) * mask[token=col]
    tgemm<5,1,true><<<dim3(SS/128, MM/128, 32), 512, SMEM_REQ>>>(
        bproj, bk_h, nullptr, bkpT_h, nullptr, mask, inv_sqrt_m,
        KK, KK, HK, SS,
        0, 0, (long long)SS*HK, KK,
        (long long)HH*MM*SS, (long long)MM*SS, 0);

    // 6. kv partials + reduce -> kvT
    tgemm<3,8,false><<<dim3(1, MM/128, 32*8), 512, SMEM_REQ>>>(
        bkpT_h, bvT_h, part, nullptr, nullptr, nullptr, 1.0f,
        SS, SS, SS, KK,
        (long long)HH*MM*SS, (long long)MM*SS, (long long)HH*KK*SS, (long long)KK*SS,
        2097152LL, 262144LL, 32768LL);
    reduce_kvT_kernel<<<dim3(32, 8), 256>>>(part, bkvT_h);

    // 7. ksum from kpT
    ksum_kernel<<<dim3(32, 32), 256>>>(bkpT_h, ks);

    // 8. fused qp + denom + attn
    fattn_kernel<<<dim3(1, SS/64, 32), 256, SMEM_FATTN>>>(
        bq_h, bproj, bkvT_h, ks, bat_h);

    // 9. ao = attn @ WoT + bo
    tgemm<0,1,false><<<dim3(1, BS/128, 1), 512, SMEM_REQ>>>(
        bat_h, bWoT, ao, nullptr, bo, nullptr, 1.0f,
        HK, HK, HK, DD, 0,0,0,0, 0,0,0);

    // 10+11. fused double LN
    ln_double_kernel<<<BS, 128>>>(Xn, ao, mask, ln2_g, ln2_b, fln0_g, fln0_b, btA_h);

    // 12-14. FFN
    tgemm<1,1,false><<<dim3(1, BS/128, 1), 512, SMEM_REQ>>>(
        btA_h, bfw0T, tB, nullptr, f_b0, nullptr, 1.0f,
        DD, DD, DD, DD, 0,0,0,0, 0,0,0);
    ln_kernel<<<BS, 128>>>(tB, fln1_g, fln1_b, nullptr, btA_h);
    tgemm<0,1,false><<<dim3(1, BS/128, 1), 512, SMEM_REQ>>>(
        btA_h, bfw1T, out, nullptr, f_b1, nullptr, 1.0f,
        DD, DD, DD, DD, 0,0,0,0, 0,0,0);
}

// round 13
// speedup vs baseline: 1.8308x; 1.0105x over previous
#include <cuda_runtime.h>
#include <cuda_fp16.h>
#include <math.h>
#include <stdint.h>

// Problem constants
#define BB 4
#define SS 4096
#define DD 128
#define HH 8
#define KK 128
#define MM 256

#define BS   (BB*SS)        // 16384
#define BSH  (BB*SS*HH)     // 131072
#define HK   (HH*KK)        // 1024
#define HM   (HH*MM)        // 2048

typedef __half hf;

// -------- scratch (static device globals) --------
__device__ float g_Xn  [BS*DD];
__device__ float g_part[2097152];              // kv split-K partials
__device__ float g_ks  [BB*HH*MM];

// fp16 buffers
__device__ hf b_Q   [BS*DD];
__device__ hf b_Xn  [BS*DD];
__device__ hf b_WqT [HK*DD];
__device__ hf b_WkT [HK*DD];
__device__ hf b_WvT [HK*DD];
__device__ hf b_WoT [DD*HK];
__device__ hf b_proj[MM*KK];
__device__ hf b_fw0T[DD*DD];
__device__ hf b_fw1T[DD*DD];
__device__ hf b_q   [BS*HK];
__device__ hf b_k   [BS*HK];
__device__ hf b_kpT [(size_t)BSH*MM];     // [b,h,m,s]
__device__ hf b_vT  [BS*HK];              // [b,h,k,s]
__device__ hf b_kvT [BB*HH*KK*MM];        // [b,h,k,m]
__device__ hf b_attn[(size_t)BS*HK];      // [b,s,h,k]
__device__ hf b_tA  [BS*DD];
__device__ hf b_tB  [BS*DD];

// ================= asm helpers =================
__device__ __forceinline__ uint32_t smem_u32(const void* p) {
    uint32_t a;
    asm("{ .reg .u64 t; cvta.to.shared.u64 t, %1; cvt.u32.u64 %0, t; }" : "=r"(a) : "l"(p));
    return a;
}
#define CP_ASYNC16(dst, src) asm volatile("cp.async.cg.shared.global [%0], [%1], 16;" :: "r"(dst), "l"(__cvta_generic_to_global(src)))
#define CP_COMMIT()          asm volatile("cp.async.commit_group;")
#define CP_WAIT(n)           asm volatile("cp.async.wait_group %0;" :: "n"(n))

__device__ __forceinline__ void ldsm4(uint32_t* r, uint32_t a) {
    asm volatile("ldmatrix.sync.aligned.m8n8.x4.shared.b16 {%0,%1,%2,%3}, [%4];"
        : "=r"(r[0]), "=r"(r[1]), "=r"(r[2]), "=r"(r[3]) : "r"(a));
}
__device__ __forceinline__ void mma_f16(float* d, const uint32_t* a, const uint32_t* b) {
    asm volatile("mma.sync.aligned.m16n8k16.row.col.f32.f16.f16.f32 "
        "{%0,%1,%2,%3}, {%4,%5,%6,%7}, {%8,%9}, {%0,%1,%2,%3};"
        : "+f"(d[0]), "+f"(d[1]), "+f"(d[2]), "+f"(d[3])
        : "r"(a[0]), "r"(a[1]), "r"(a[2]), "r"(a[3]), "r"(b[0]), "r"(b[1]));
}
__device__ __forceinline__ void st_h2(hf* p, float a, float b) {
    *reinterpret_cast<__half2*>(p) = __halves2half2(__float2half(a), __float2half(b));
}

// ---------------- chunk-tile loader ----------------
template<int R, int NTHR>
__device__ __forceinline__ void load_ct(uint32_t sU,
    const hf* __restrict__ G, int ld, int base0, int k0, int tid)
{
    #pragma unroll
    for (int i = 0; i < (R*8)/NTHR; i++) {
        int idx = tid + i*NTHR;
        int r = idx >> 3, c16 = idx & 7;
        const hf* src = G + (size_t)(base0 + r)*ld + k0 + c16*8;
        int off = r*128 + c16*16;
        int sw = off ^ ((off >> 3) & 0x70);
        CP_ASYNC16(sU + sw, src);
    }
}

// ================= fp16 warp-MMA GEMM (512 thr, 3-stage) =================
// 128x128 CTA tile, K-tiles of 64, 16 warps 4(m)x4(n), warp tile 32m x 32n.
// EPI 0: (acc + bias[col]) * alpha                 -> fp32 C or fp16 Ch
// EPI 3: acc (split-K partial)                     -> fp32 C
// EPI 5: (elu(acc)+1) * alpha * maskf[b*S+col]     -> fp16 Ch
// EPI 6: acc + bias[h*128+row]                     -> fp16 Ch
// EPI 7: fused Wo: y = LN(LN(resid + (acc+bias)*mask[row]; lnA); lnB) -> fp16 Ch
// EPI 8: fused FFN1: y = LN(elu(acc+bias); lnA)                        -> fp16 Ch
template<int EPI, int NSPLIT, bool OUTB>
__global__ void __launch_bounds__(512) tgemm(
    const hf* __restrict__ Ah, const hf* __restrict__ Bh,
    float* __restrict__ C, hf* __restrict__ Ch,
    const float* __restrict__ bias, const int* __restrict__ mask,
    const float* __restrict__ resid,
    const float* __restrict__ lnAg, const float* __restrict__ lnAb,
    const float* __restrict__ lnBg, const float* __restrict__ lnBb,
    float alpha,
    int Kd, int lda, int ldb, int ldc,
    long long sAb, long long sAh2, long long sBb, long long sBh2,
    long long sCb, long long sCh2, long long sCs)
{
    extern __shared__ char dyn[];
    const int ASZ = 128*128;        // 16KB per tile
    const int BUFSZ = 2*ASZ;        // A, B = 32KB

    uint32_t dynU = smem_u32(dyn);
    uint32_t smU = (dynU + 1023u) & ~1023u;

    int tid = threadIdx.x;
    int lane = tid & 31, wid = tid >> 5;
    int wm = (wid & 3) * 32, wn = (wid >> 2) * 32;

    int z = blockIdx.z;
    int split = z % NSPLIT, bh = z / NSPLIT;
    int b = bh >> 3, h = bh & 7;
    Ah += (long long)b*sAb + (long long)h*sAh2;
    Bh += (long long)b*sBb + (long long)h*sBh2;
    long long coff = (long long)b*sCb + (long long)h*sCh2 + (long long)split*sCs;
    if (OUTB) { Ch += coff; } else { C += coff; }
    int kchunk = Kd / NSPLIT;
    int kbeg = split * kchunk;
    int nk = kchunk / 64;
    int m0 = blockIdx.y * 128, n0 = blockIdx.x * 128;

    float acc[2][4][4] = {};

    auto copy_stage = [&](int st, int k0) {
        uint32_t dU = smU + st*BUFSZ;
        load_ct<128,512>(dU,       Ah, lda, m0, k0, tid);
        load_ct<128,512>(dU + ASZ, Bh, ldb, n0, k0, tid);
    };

    copy_stage(0, kbeg);            CP_COMMIT();
    copy_stage(1, kbeg + 64);       CP_COMMIT();

    int rA = wm + (lane & 15);
    int cA = lane >> 4;
    int rB = wn + (lane & 7) + ((lane >> 4) & 1) * 8;
    int cB = (lane >> 3) & 1;

    for (int it = 0; it < nk; it++) {
        if (it < nk - 1) { CP_WAIT(1); } else { CP_WAIT(0); }
        __syncthreads();
        if (it + 2 < nk) {
            copy_stage((it + 2) % 3, kbeg + (it+2)*64);
            CP_COMMIT();
        }
        uint32_t aH = smU + (it % 3)*BUFSZ;
        uint32_t bH = aH + ASZ;
        #pragma unroll
        for (int ks = 0; ks < 4; ks++) {
            uint32_t afh[2][4], bfh[4][2];
            #pragma unroll
            for (int mi = 0; mi < 2; mi++) {
                int row = rA + mi*16;
                int sw = row*128 + (((ks*2 + cA) ^ (row & 7)) * 16);
                ldsm4(afh[mi], aH + sw);
            }
            #pragma unroll
            for (int nj = 0; nj < 2; nj++) {
                int row = rB + nj*16;
                int sw = row*128 + (((ks*2 + cB) ^ (row & 7)) * 16);
                ldsm4(&bfh[nj*2][0], bH + sw);
            }
            #pragma unroll
            for (int mi = 0; mi < 2; mi++)
                #pragma unroll
                for (int ni = 0; ni < 4; ni++)
                    mma_f16(acc[mi][ni], afh[mi], bfh[ni]);
        }
        __syncthreads();
    }

    if (EPI == 7 || EPI == 8) {
        // fused epilogue: acc -> fp32 smem tile -> row LN(s) -> fp16 global
        float* smf = reinterpret_cast<float*>(dyn + (smU - dynU));
        #pragma unroll
        for (int mi = 0; mi < 2; mi++) {
            int r0l = wm + mi*16 + (lane >> 2);
            int r1l = r0l + 8;
            int r0g = m0 + r0l, r1g = m0 + r1l;
            float mk0 = 1.0f, mk1 = 1.0f;
            if (EPI == 7) { mk0 = (float)mask[r0g]; mk1 = (float)mask[r1g]; }
            #pragma unroll
            for (int ni = 0; ni < 4; ni++) {
                int c0 = wn + ni*8 + (lane & 3)*2;     // N==128, n0==0
                float d0 = acc[mi][ni][0] + bias[c0];
                float d1 = acc[mi][ni][1] + bias[c0+1];
                float d2 = acc[mi][ni][2] + bias[c0];
                float d3 = acc[mi][ni][3] + bias[c0+1];
                if (EPI == 7) {
                    d0 = resid[(size_t)r0g*DD + c0]     + d0*mk0;
                    d1 = resid[(size_t)r0g*DD + c0 + 1] + d1*mk0;
                    d2 = resid[(size_t)r1g*DD + c0]     + d2*mk1;
                    d3 = resid[(size_t)r1g*DD + c0 + 1] + d3*mk1;
                } else {
                    d0 = d0 > 0.0f ? d0 : expm1f(d0);
                    d1 = d1 > 0.0f ? d1 : expm1f(d1);
                    d2 = d2 > 0.0f ? d2 : expm1f(d2);
                    d3 = d3 > 0.0f ? d3 : expm1f(d3);
                }
                smf[r0l*132 + c0] = d0; smf[r0l*132 + c0+1] = d1;
                smf[r1l*132 + c0] = d2; smf[r1l*132 + c0+1] = d3;
            }
        }
        __syncthreads();
        int row = tid >> 2, sub = tid & 3;
        float* rp = smf + row*132 + sub*32;
        // LN A
        float s = 0.0f;
        #pragma unroll
        for (int j = 0; j < 32; j++) s += rp[j];
        s += __shfl_xor_sync(0xffffffffu, s, 1);
        s += __shfl_xor_sync(0xffffffffu, s, 2);
        float mu = s * (1.0f/128.0f);
        float s2 = 0.0f;
        #pragma unroll
        for (int j = 0; j < 32; j++) { float d = rp[j] - mu; s2 += d*d; }
        s2 += __shfl_xor_sync(0xffffffffu, s2, 1);
        s2 += __shfl_xor_sync(0xffffffffu, s2, 2);
        float rs = rsqrtf(s2 * (1.0f/128.0f) + 1e-3f);
        if (EPI == 8) {
            #pragma unroll
            for (int j = 0; j < 32; j += 2) {
                int c = sub*32 + j;
                float y0 = (rp[j]   - mu)*rs*lnAg[c]   + lnAb[c];
                float y1 = (rp[j+1] - mu)*rs*lnAg[c+1] + lnAb[c+1];
                st_h2(Ch + (size_t)(m0 + row)*DD + c, y0, y1);
            }
        } else {
            float t = 0.0f;
            #pragma unroll
            for (int j = 0; j < 32; j++) {
                int c = sub*32 + j;
                float y = (rp[j] - mu)*rs*lnAg[c] + lnAb[c];
                rp[j] = y; t += y;
            }
            t += __shfl_xor_sync(0xffffffffu, t, 1);
            t += __shfl_xor_sync(0xffffffffu, t, 2);
            float mu2 = t * (1.0f/128.0f);
            float v2 = 0.0f;
            #pragma unroll
            for (int j = 0; j < 32; j++) { float d = rp[j] - mu2; v2 += d*d; }
            v2 += __shfl_xor_sync(0xffffffffu, v2, 1);
            v2 += __shfl_xor_sync(0xffffffffu, v2, 2);
            float rs2 = rsqrtf(v2 * (1.0f/128.0f) + 1e-3f);
            #pragma unroll
            for (int j = 0; j < 32; j += 2) {
                int c = sub*32 + j;
                float y0 = (rp[j]   - mu2)*rs2*lnBg[c]   + lnBb[c];
                float y1 = (rp[j+1] - mu2)*rs2*lnBg[c+1] + lnBb[c+1];
                st_h2(Ch + (size_t)(m0 + row)*DD + c, y0, y1);
            }
        }
        return;
    }

    // standard epilogue
    #pragma unroll
    for (int mi = 0; mi < 2; mi++) {
        int r0 = m0 + wm + mi*16 + (lane >> 2);
        int r1 = r0 + 8;
        float f0 = 1.0f, f1 = 1.0f;
        if (EPI == 6) {
            f0 = bias[(h << 7) + r0];
            f1 = bias[(h << 7) + r1];
        }
        #pragma unroll
        for (int ni = 0; ni < 4; ni++) {
            int c0 = n0 + wn + ni*8 + (lane & 3)*2;
            float d0 = acc[mi][ni][0], d1 = acc[mi][ni][1];
            float d2 = acc[mi][ni][2], d3 = acc[mi][ni][3];
            if (EPI == 0) {
                float b0 = bias ? bias[c0] : 0.0f, b1 = bias ? bias[c0+1] : 0.0f;
                d0 = (d0 + b0)*alpha; d1 = (d1 + b1)*alpha;
                d2 = (d2 + b0)*alpha; d3 = (d3 + b1)*alpha;
            } else if (EPI == 5) {
                float m0f = (float)mask[b*SS + c0];
                float m1f = (float)mask[b*SS + c0 + 1];
                d0 = (d0 > 0.0f ? d0 + 1.0f : expf(d0)) * alpha * m0f;
                d1 = (d1 > 0.0f ? d1 + 1.0f : expf(d1)) * alpha * m1f;
                d2 = (d2 > 0.0f ? d2 + 1.0f : expf(d2)) * alpha * m0f;
                d3 = (d3 > 0.0f ? d3 + 1.0f : expf(d3)) * alpha * m1f;
            } else if (EPI == 6) {
                d0 += f0; d1 += f0; d2 += f1; d3 += f1;
            }
            if (OUTB) {
                st_h2(Ch + (size_t)r0*ldc + c0, d0, d1);
                st_h2(Ch + (size_t)r1*ldc + c0, d2, d3);
            } else {
                *reinterpret_cast<float2*>(C + (size_t)r0*ldc + c0) = make_float2(d0, d1);
                *reinterpret_cast<float2*>(C + (size_t)r1*ldc + c0) = make_float2(d2, d3);
            }
        }
    }
}

// ================= fused qp + denom + attn kernel (256 threads) =================
#define FA_QP   0
#define FA_QT   32768
#define FA_BBUF 49152
#define SMEM_FATTN (81920 + 1024)

__global__ void __launch_bounds__(256) fattn_kernel(
    const hf* __restrict__ qh,
    const hf* __restrict__ projh,
    const hf* __restrict__ kvh,
    const float* __restrict__ ksum,
    hf* __restrict__ outh)
{
    extern __shared__ char dyn[];
    __shared__ float dn_smem[64];
    uint32_t dynU = smem_u32(dyn);
    uint32_t smU = (dynU + 1023u) & ~1023u;

    int tid = threadIdx.x;
    int lane = tid & 31, wid = tid >> 5;
    int ws = wid & 1, wn = wid >> 1;

    int bh = blockIdx.z;
    int b = bh >> 3, h = bh & 7;
    int s0 = blockIdx.y * 64;

    const hf* qhp = qh + ((size_t)(b*SS + s0))*HK + h*KK;
    const hf* kvhp = kvh + (size_t)bh*KK*MM;
    const float* ksp = ksum + bh*MM;

    const float inv_sqrt_m = 0.0625f;

    load_ct<64,256>(smU + FA_QT,        qhp, HK, 0, 0,  tid);
    load_ct<64,256>(smU + FA_QT + 8192, qhp, HK, 0, 64, tid);

    auto loadB = [&](int it) {
        uint32_t dU = smU + FA_BBUF + (it & 1)*16384;
        if (it < 4) {
            int mh = it >> 1, kt = it & 1;
            load_ct<128,256>(dU, projh, KK, mh*128, kt*64, tid);
        } else {
            int ch = it - 4;
            load_ct<128,256>(dU, kvhp, MM, 0, ch*64, tid);
        }
    };

    loadB(0); CP_COMMIT();
    loadB(1); CP_COMMIT();

    int rAl = ws*32 + (lane & 15);
    int cA  = lane >> 4;
    int rBl = wn*32 + (lane & 7) + ((lane >> 4) & 1) * 8;
    int cB  = (lane >> 3) & 1;

    float acc[2][4][4] = {};

    for (int it = 0; it < 8; it++) {
        if (it < 7) { CP_WAIT(1); } else { CP_WAIT(0); }
        __syncthreads();

        uint32_t aH;
        if (it < 4) {
            int kt = it & 1;
            aH = smU + FA_QT + kt*8192;
        } else {
            int ch = it - 4;
            aH = smU + FA_QP + ch*8192;
        }
        uint32_t bH = smU + FA_BBUF + (it & 1)*16384;

        #pragma unroll
        for (int ks = 0; ks < 4; ks++) {
            uint32_t afh[2][4], bfh[4][2];
            #pragma unroll
            for (int mi = 0; mi < 2; mi++) {
                int row = rAl + mi*16;
                int sw = row*128 + (((ks*2 + cA) ^ (row & 7)) * 16);
                ldsm4(afh[mi], aH + sw);
            }
            #pragma unroll
            for (int nj = 0; nj < 2; nj++) {
                int row = rBl + nj*16;
                int sw = row*128 + (((ks*2 + cB) ^ (row & 7)) * 16);
                ldsm4(&bfh[nj*2][0], bH + sw);
            }
            #pragma unroll
            for (int mi = 0; mi < 2; mi++)
                #pragma unroll
                for (int ni = 0; ni < 4; ni++)
                    mma_f16(acc[mi][ni], afh[mi], bfh[ni]);
        }

        if (it == 1 || it == 3) {
            int mh = it >> 1;
            char* base = dyn + (smU - dynU);
            #pragma unroll
            for (int mi = 0; mi < 2; mi++) {
                int r0 = ws*32 + mi*16 + (lane >> 2);
                int r1 = r0 + 8;
                #pragma unroll
                for (int ni = 0; ni < 4; ni++) {
                    int cl = wn*32 + ni*8 + (lane & 3)*2;
                    int mg = mh*128 + cl;
                    int chunk = mg >> 6, cin = mg & 63;
                    float d0 = acc[mi][ni][0], d1 = acc[mi][ni][1];
                    float d2 = acc[mi][ni][2], d3 = acc[mi][ni][3];
                    d0 = (d0 > 0.0f ? d0 + 1.0f : expf(d0)) * inv_sqrt_m;
                    d1 = (d1 > 0.0f ? d1 + 1.0f : expf(d1)) * inv_sqrt_m;
                    d2 = (d2 > 0.0f ? d2 + 1.0f : expf(d2)) * inv_sqrt_m;
                    d3 = (d3 > 0.0f ? d3 + 1.0f : expf(d3)) * inv_sqrt_m;
                    int o0 = r0*128 + cin*2;  int sw0 = o0 ^ ((o0 >> 3) & 0x70);
                    int o1 = r1*128 + cin*2;  int sw1 = o1 ^ ((o1 >> 3) & 0x70);
                    st_h2(reinterpret_cast<hf*>(base + FA_QP + chunk*8192 + sw0), d0, d1);
                    st_h2(reinterpret_cast<hf*>(base + FA_QP + chunk*8192 + sw1), d2, d3);
                }
            }
            #pragma unroll
            for (int mi = 0; mi < 2; mi++)
                #pragma unroll
                for (int ni = 0; ni < 4; ni++)
                    #pragma unroll
                    for (int c = 0; c < 4; c++)
                        acc[mi][ni][c] = 0.0f;
        }

        __syncthreads();

        if (it == 3) {
            int row = tid >> 2, part = tid & 3;
            char* base = dyn + (smU - dynU);
            float s = 0.0f;
            for (int j = 0; j < 64; j++) {
                int o = row*128 + j*2;
                int sw = o ^ ((o >> 3) & 0x70);
                float hv = __half2float(*reinterpret_cast<hf*>(base + FA_QP + part*8192 + sw));
                s += hv * ksp[part*64 + j];
            }
            s += __shfl_down_sync(0xffffffffu, s, 1);
            s += __shfl_down_sync(0xffffffffu, s, 2);
            if (part == 0) dn_smem[row] = 1.0f / (s + 1e-6f);
            __syncthreads();
        }

        if (it + 2 < 8) { loadB(it + 2); CP_COMMIT(); }
    }

    #pragma unroll
    for (int mi = 0; mi < 2; mi++) {
        int r0 = ws*32 + mi*16 + (lane >> 2);
        int r1 = r0 + 8;
        float f0 = dn_smem[r0], f1 = dn_smem[r1];
        #pragma unroll
        for (int ni = 0; ni < 4; ni++) {
            int ck = wn*32 + ni*8 + (lane & 3)*2;
            size_t a0 = ((size_t)(b*SS + s0 + r0))*HK + h*KK + ck;
            size_t a1 = ((size_t)(b*SS + s0 + r1))*HK + h*KK + ck;
            st_h2(outh + a0, acc[mi][ni][0]*f0, acc[mi][ni][1]*f0);
            st_h2(outh + a1, acc[mi][ni][2]*f1, acc[mi][ni][3]*f1);
        }
    }
}

// ---------------- converts ----------------
__global__ void conv_kernel(const float* __restrict__ src, hf* __restrict__ hi, int n)
{
    int i = blockIdx.x*256 + threadIdx.x;
    if (i < n) hi[i] = __float2half(src[i]);
}
__global__ void convT3_kernel(const float* __restrict__ s0, const float* __restrict__ s1,
                              const float* __restrict__ s2,
                              hf* __restrict__ h0, hf* __restrict__ h1, hf* __restrict__ h2,
                              int R, int C)
{
    const float* src = blockIdx.y == 0 ? s0 : (blockIdx.y == 1 ? s1 : s2);
    hf* hi = blockIdx.y == 0 ? h0 : (blockIdx.y == 1 ? h1 : h2);
    if (src == nullptr) return;
    int i = blockIdx.x*256 + threadIdx.x;
    if (i < R*C) {
        int r = i / C, c = i % C;
        hi[(size_t)c*R + r] = __float2half(src[i]);
    }
}
__global__ void convT_kernel(const float* __restrict__ src, hf* __restrict__ hi, int R, int C)
{
    int i = blockIdx.x*256 + threadIdx.x;
    if (i < R*C) {
        int r = i / C, c = i % C;
        hi[(size_t)c*R + r] = __float2half(src[i]);
    }
}

// ---------------- LayerNorm (only for Xn now) ----------------
__global__ void ln_kernel(const float* __restrict__ in1,
                          const float* __restrict__ gamma, const float* __restrict__ beta,
                          float* __restrict__ outf, hf* __restrict__ outh)
{
    int row = blockIdx.x;
    int t = threadIdx.x;
    __shared__ float smv[4];
    float x = in1[(size_t)row*DD + t];
    float s = x;
    #pragma unroll
    for (int o = 16; o; o >>= 1) s += __shfl_down_sync(0xffffffffu, s, o);
    if ((t & 31) == 0) smv[t >> 5] = s;
    __syncthreads();
    float mu = (smv[0] + smv[1] + smv[2] + smv[3]) * (1.0f/128.0f);
    float d = x - mu;
    float s2 = d * d;
    __syncthreads();
    #pragma unroll
    for (int o = 16; o; o >>= 1) s2 += __shfl_down_sync(0xffffffffu, s2, o);
    if ((t & 31) == 0) smv[t >> 5] = s2;
    __syncthreads();
    float var = (smv[0] + smv[1] + smv[2] + smv[3]) * (1.0f/128.0f);
    float y = d * rsqrtf(var + 1e-3f) * gamma[t] + beta[t];
    size_t idx = (size_t)row*DD + t;
    if (outf) outf[idx] = y;
    if (outh) outh[idx] = __float2half(y);
}

// ---------------- kv reduce + transpose ----------------
__global__ void reduce_kvT_kernel(const float* __restrict__ part, hf* __restrict__ hi)
{
    int bh = blockIdx.x;
    int tm = (blockIdx.y >> 1) * 64;
    int tk = (blockIdx.y & 1) * 64;
    __shared__ float t[64][65];
    const float* p = part + (size_t)bh*8*32768;
    int tid = threadIdx.x;
    #pragma unroll
    for (int i = 0; i < 16; i++) {
        int idx = tid + i*256;
        int r = idx >> 6, c = idx & 63;
        float s = 0.0f;
        #pragma unroll
        for (int sp = 0; sp < 8; sp++) s += p[sp*32768 + (tm+r)*128 + tk+c];
        t[c][r] = s;
    }
    __syncthreads();
    hf* H = hi + (size_t)bh*KK*MM;
    #pragma unroll
    for (int i = 0; i < 16; i++) {
        int idx = tid + i*256;
        int kk2 = idx >> 6, mm2 = idx & 63;
        H[(size_t)(tk+kk2)*MM + tm+mm2] = __float2half(t[kk2][mm2]);
    }
}

// ---------------- ksum from kpT ----------------
__global__ void ksum_kernel(const hf* __restrict__ kph, float* __restrict__ ks)
{
    int bh = blockIdx.x;
    int wid = threadIdx.x >> 5, lane = threadIdx.x & 31;
    int m = blockIdx.y * 8 + wid;
    const hf* H = kph + ((size_t)bh*MM + m)*SS;
    float s = 0.0f;
    for (int i = lane; i < SS; i += 32)
        s += __half2float(H[i]);
    #pragma unroll
    for (int o = 16; o; o >>= 1) s += __shfl_down_sync(0xffffffffu, s, o);
    if (lane == 0) ks[bh*MM + m] = s;
}

// ---------------- host-side launch ----------------
template<typename T>
static T* sym_addr(const void* sym)
{
    void* p = nullptr;
    cudaGetSymbolAddress(&p, sym);
    return (T*)p;
}

#define SMEM_REQ (3*2*128*128 + 1024)   // 99328 (also covers 128*132*4=67.6KB epilogue tile)

extern "C" void kernel_launch(void* const* d_in, const int* in_sizes, int n_in,
                              void* d_out, int out_size)
{
    (void)in_sizes; (void)n_in; (void)out_size;
    const float* Q      = (const float*)d_in[0];
    const float* X      = (const float*)d_in[1];
    const int*   mask   = (const int*)  d_in[2];
    const float* Wq     = (const float*)d_in[3];
    const float* bq     = (const float*)d_in[4];
    const float* Wk     = (const float*)d_in[5];
    const float* bk     = (const float*)d_in[6];
    const float* Wv     = (const float*)d_in[7];
    const float* bv     = (const float*)d_in[8];
    const float* Wo     = (const float*)d_in[9];
    const float* bo     = (const float*)d_in[10];
    const float* proj   = (const float*)d_in[11];
    const float* ln1_g  = (const float*)d_in[12];
    const float* ln1_b  = (const float*)d_in[13];
    const float* ln2_g  = (const float*)d_in[14];
    const float* ln2_b  = (const float*)d_in[15];
    const float* fln0_g = (const float*)d_in[16];
    const float* fln0_b = (const float*)d_in[17];
    const float* f_w0   = (const float*)d_in[18];
    const float* f_b0   = (const float*)d_in[19];
    const float* fln1_g = (const float*)d_in[20];
    const float* fln1_b = (const float*)d_in[21];
    const float* f_w1   = (const float*)d_in[22];
    const float* f_b1   = (const float*)d_in[23];
    float* out = (float*)d_out;

    float* Xn   = sym_addr<float>(g_Xn);
    float* part = sym_addr<float>(g_part);
    float* ks   = sym_addr<float>(g_ks);

    hf* bQ    = sym_addr<hf>(b_Q);
    hf* bXn   = sym_addr<hf>(b_Xn);
    hf* bWqT  = sym_addr<hf>(b_WqT);
    hf* bWkT  = sym_addr<hf>(b_WkT);
    hf* bWvT  = sym_addr<hf>(b_WvT);
    hf* bWoT  = sym_addr<hf>(b_WoT);
    hf* bproj = sym_addr<hf>(b_proj);
    hf* bfw0T = sym_addr<hf>(b_fw0T);
    hf* bfw1T = sym_addr<hf>(b_fw1T);
    hf* bq_h  = sym_addr<hf>(b_q);
    hf* bk_h  = sym_addr<hf>(b_k);
    hf* bkpT_h= sym_addr<hf>(b_kpT);
    hf* bvT_h = sym_addr<hf>(b_vT);
    hf* bkvT_h= sym_addr<hf>(b_kvT);
    hf* bat_h = sym_addr<hf>(b_attn);
    hf* btA_h = sym_addr<hf>(b_tA);
    hf* btB_h = sym_addr<hf>(b_tB);

    const float scale_q    = 0.08838834764831845f;  // 1/sqrt(128)
    const float inv_sqrt_m = 0.0625f;               // 1/sqrt(256)

    cudaFuncSetAttribute(tgemm<0,1,true >, cudaFuncAttributeMaxDynamicSharedMemorySize, SMEM_REQ);
    cudaFuncSetAttribute(tgemm<5,1,true >, cudaFuncAttributeMaxDynamicSharedMemorySize, SMEM_REQ);
    cudaFuncSetAttribute(tgemm<6,1,true >, cudaFuncAttributeMaxDynamicSharedMemorySize, SMEM_REQ);
    cudaFuncSetAttribute(tgemm<3,8,false>, cudaFuncAttributeMaxDynamicSharedMemorySize, SMEM_REQ);
    cudaFuncSetAttribute(tgemm<7,1,true >, cudaFuncAttributeMaxDynamicSharedMemorySize, SMEM_REQ);
    cudaFuncSetAttribute(tgemm<8,1,true >, cudaFuncAttributeMaxDynamicSharedMemorySize, SMEM_REQ);
    cudaFuncSetAttribute(tgemm<0,1,false>, cudaFuncAttributeMaxDynamicSharedMemorySize, SMEM_REQ);
    cudaFuncSetAttribute(fattn_kernel, cudaFuncAttributeMaxDynamicSharedMemorySize, SMEM_FATTN);

    // 0. converts
    conv_kernel<<<(BS*DD + 255)/256, 256>>>(Q, bQ, BS*DD);
    conv_kernel<<<(MM*KK + 255)/256, 256>>>(proj, bproj, MM*KK);
    convT3_kernel<<<dim3((DD*HK + 255)/256, 3), 256>>>(
        Wq, Wk, Wv, bWqT, bWkT, bWvT, DD, HK);
    convT_kernel<<<(HK*DD + 255)/256, 256>>>(Wo, bWoT, HK, DD);
    convT3_kernel<<<dim3((DD*DD + 255)/256, 3), 256>>>(
        f_w0, f_w1, nullptr, bfw0T, bfw1T, nullptr, DD, DD);

    // 1. Xn = LN(X; ln1)
    ln_kernel<<<BS, 128>>>(X, ln1_g, ln1_b, Xn, bXn);

    // 2-3. q, k projections -> fp16 [BS, HK]
    tgemm<0,1,true><<<dim3(HK/128, BS/128, 1), 512, SMEM_REQ>>>(
        bQ, bWqT, nullptr, bq_h, bq, nullptr, nullptr, nullptr, nullptr, nullptr, nullptr, scale_q,
        DD, DD, DD, HK, 0,0,0,0, 0,0,0);
    tgemm<0,1,true><<<dim3(HK/128, BS/128, 1), 512, SMEM_REQ>>>(
        bXn, bWkT, nullptr, bk_h, bk, nullptr, nullptr, nullptr, nullptr, nullptr, nullptr, 1.0f,
        DD, DD, DD, HK, 0,0,0,0, 0,0,0);

    // 4. vT[b,h,k,s] = Wv^T(h) @ Xn^T(b) + bv[h,k]
    tgemm<6,1,true><<<dim3(SS/128, 1, 32), 512, SMEM_REQ>>>(
        bWvT, bXn, nullptr, bvT_h, bv, nullptr, nullptr, nullptr, nullptr, nullptr, nullptr, 1.0f,
        DD, DD, DD, SS,
        0, (long long)KK*DD, (long long)SS*DD, 0,
        (long long)HH*KK*SS, (long long)KK*SS, 0);

    // 5. kpT[b,h,m,s] = (elu(proj @ k^T)+1)/sqrt(M) * mask[token=col]
    tgemm<5,1,true><<<dim3(SS/128, MM/128, 32), 512, SMEM_REQ>>>(
        bproj, bk_h, nullptr, bkpT_h, nullptr, mask, nullptr, nullptr, nullptr, nullptr, nullptr, inv_sqrt_m,
        KK, KK, HK, SS,
        0, 0, (long long)SS*HK, KK,
        (long long)HH*MM*SS, (long long)MM*SS, 0);

    // 6. kv partials + reduce -> kvT
    tgemm<3,8,false><<<dim3(1, MM/128, 32*8), 512, SMEM_REQ>>>(
        bkpT_h, bvT_h, part, nullptr, nullptr, nullptr, nullptr, nullptr, nullptr, nullptr, nullptr, 1.0f,
        SS, SS, SS, KK,
        (long long)HH*MM*SS, (long long)MM*SS, (long long)HH*KK*SS, (long long)KK*SS,
        2097152LL, 262144LL, 32768LL);
    reduce_kvT_kernel<<<dim3(32, 8), 256>>>(part, bkvT_h);

    // 7. ksum from kpT
    ksum_kernel<<<dim3(32, 32), 256>>>(bkpT_h, ks);

    // 8. fused qp + denom + attn
    fattn_kernel<<<dim3(1, SS/64, 32), 256, SMEM_FATTN>>>(
        bq_h, bproj, bkvT_h, ks, bat_h);

    // 9. fused Wo-GEMM + residual + double LN -> tA (fp16)
    tgemm<7,1,true><<<dim3(1, BS/128, 1), 512, SMEM_REQ>>>(
        bat_h, bWoT, nullptr, btA_h, bo, mask, Xn, ln2_g, ln2_b, fln0_g, fln0_b, 1.0f,
        HK, HK, HK, DD, 0,0,0,0, 0,0,0);

    // 10. fused FFN1-GEMM + elu + LN -> tB (fp16)
    tgemm<8,1,true><<<dim3(1, BS/128, 1), 512, SMEM_REQ>>>(
        btA_h, bfw0T, nullptr, btB_h, f_b0, nullptr, nullptr, fln1_g, fln1_b, nullptr, nullptr, 1.0f,
        DD, DD, DD, DD, 0,0,0,0, 0,0,0);

    // 11. FFN2 -> out (fp32)
    tgemm<0,1,false><<<dim3(1, BS/128, 1), 512, SMEM_REQ>>>(
        btB_h, bfw1T, out, nullptr, f_b1, nullptr, nullptr, nullptr, nullptr, nullptr, nullptr, 1.0f,
        DD, DD, DD, DD, 0,0,0,0, 0,0,0);
}